// round 5
// baseline (speedup 1.0000x reference)
#include <cuda_runtime.h>
#include <cstdint>

#define N_EXPERTS 16
#define D_MODEL   1024
#define D_FF      2816
#define N_TOKENS  8192
#define TOP_K     2
#define A_TOTAL   (N_TOKENS * TOP_K)

#define BM 128
#define BK 32
#define BN 128

#define T_STRIDE 40                 // smem row stride (floats); LDS.64 banks (8g+2t) distinct
#define T_STAGE  (128 * T_STRIDE)   // 5120 floats per tile stage (A and B identical shape)

#define MAX_SLOTS  (A_TOTAL + N_EXPERTS * BM)  // 18432
#define MAX_MTILES (MAX_SLOTS / BM)            // 144

// ---------------- scratch (device globals) ----------------
__device__ int   g_perm[MAX_SLOTS];
__device__ float g_wgt[MAX_SLOTS];
__device__ int   g_counts[N_EXPERTS];
__device__ int   g_offsets[N_EXPERTS];
__device__ int   g_tile_expert[MAX_MTILES];
__device__ float g_Xr [(size_t)N_TOKENS * D_MODEL];           // tf32-rounded, k-interleaved
__device__ float g_H  [(size_t)MAX_SLOTS * D_FF];             // tf32-rounded, k-interleaved
__device__ float g_W1t[(size_t)N_EXPERTS * D_FF * D_MODEL];   // [e][f][d'] rounded
__device__ float g_W2t[(size_t)N_EXPERTS * D_FF * D_MODEL];   // [e][f][d'] rounded
__device__ float g_W3t[(size_t)N_EXPERTS * D_MODEL * D_FF];   // [e][d][f'] rounded

// ---------------- helpers ----------------
__device__ __forceinline__ uint32_t f2tf(float f) {
    uint32_t r;
    asm("cvt.rna.tf32.f32 %0, %1;" : "=r"(r) : "f"(f));
    return r;
}
__device__ __forceinline__ float f2tff(float f) { return __uint_as_float(f2tf(f)); }
__device__ __forceinline__ int p8(int w) { return (w < 4) ? 2 * w : 2 * (w - 4) + 1; }

__device__ __forceinline__ void mma8(float* c, const uint32_t* a, const uint32_t* b) {
    asm volatile(
        "mma.sync.aligned.m16n8k8.row.col.f32.tf32.tf32.f32 "
        "{%0,%1,%2,%3}, {%4,%5,%6,%7}, {%8,%9}, {%0,%1,%2,%3};\n"
        : "+f"(c[0]), "+f"(c[1]), "+f"(c[2]), "+f"(c[3])
        : "r"(a[0]), "r"(a[1]), "r"(a[2]), "r"(a[3]),
          "r"(b[0]), "r"(b[1]));
}
__device__ __forceinline__ float silu_f(float x) { return x / (1.0f + __expf(-x)); }
__device__ __forceinline__ uint32_t smem_u32(const void* p) {
    return (uint32_t)__cvta_generic_to_shared(p);
}
__device__ __forceinline__ void cp16(uint32_t dst, const void* src) {
    asm volatile("cp.async.cg.shared.global [%0], [%1], 16;" :: "r"(dst), "l"(src));
}
__device__ __forceinline__ void cp16_pred(uint32_t dst, const void* src, int valid) {
    int sz = valid ? 16 : 0;   // sz=0 zero-fills the 16B destination
    asm volatile("cp.async.cg.shared.global [%0], [%1], 16, %2;"
                 :: "r"(dst), "l"(src), "r"(sz));
}
#define CP_COMMIT() asm volatile("cp.async.commit_group;" ::: "memory")
#define CP_WAIT1()  asm volatile("cp.async.wait_group 1;"  ::: "memory")

// ---------------- dispatch ----------------
__global__ void init_kernel() {
    int i = blockIdx.x * blockDim.x + threadIdx.x;
    if (i < MAX_SLOTS) g_perm[i] = -1;
    if (i < N_EXPERTS) g_counts[i] = 0;
}
__global__ void zero_out_kernel(float4* __restrict__ out) {
    int i = blockIdx.x * blockDim.x + threadIdx.x;
    if (i < N_TOKENS * D_MODEL / 4) out[i] = make_float4(0.f, 0.f, 0.f, 0.f);
}
// round + interleave x: per 8-float block, store order k = 0,4,1,5 | 2,6,3,7
__global__ void round_x_kernel(const float4* __restrict__ x) {
    int i = blockIdx.x * blockDim.x + threadIdx.x;   // 8-float chunk index
    if (i < N_TOKENS * D_MODEL / 8) {
        float4 v0 = x[2 * i];
        float4 v1 = x[2 * i + 1];
        uint4 u0, u1;
        u0.x = f2tf(v0.x); u0.y = f2tf(v1.x); u0.z = f2tf(v0.y); u0.w = f2tf(v1.y);
        u1.x = f2tf(v0.z); u1.y = f2tf(v1.z); u1.z = f2tf(v0.w); u1.w = f2tf(v1.w);
        *(uint4*)&g_Xr[(size_t)i * 8]     = u0;
        *(uint4*)&g_Xr[(size_t)i * 8 + 4] = u1;
    }
}
__global__ void count_kernel(const int* __restrict__ eidx) {
    int i = blockIdx.x * blockDim.x + threadIdx.x;
    if (i < A_TOTAL) atomicAdd(&g_counts[eidx[i]], 1);
}
__global__ void scan_kernel() {
    if (threadIdx.x == 0 && blockIdx.x == 0) {
        for (int i = 0; i < MAX_MTILES; i++) g_tile_expert[i] = -1;
        int acc = 0;
        for (int e = 0; e < N_EXPERTS; e++) {
            g_offsets[e] = acc;
            int nt = (g_counts[e] + BM - 1) / BM;
            int t0 = acc / BM;
            for (int i = 0; i < nt; i++) g_tile_expert[t0 + i] = e;
            acc += nt * BM;
        }
    }
}
__global__ void scatter_kernel(const int* __restrict__ eidx,
                               const float* __restrict__ ew) {
    int i = blockIdx.x * blockDim.x + threadIdx.x;
    if (i < A_TOTAL) {
        int e = eidx[i];
        int p = atomicAdd(&g_offsets[e], 1);
        g_perm[p] = i / TOP_K;
        g_wgt[p]  = ew[i];
    }
}

// transpose + round + k-interleave: in [R][C] row-major -> out [C][R] with
// within-8 permutation applied to the R (=k) index. grid (C/32, R/32, E).
__global__ void __launch_bounds__(256)
transpose_round_kernel(const float* __restrict__ in, float* __restrict__ out,
                       int R, int C) {
    __shared__ float tile[32][33];
    const size_t mat = (size_t)R * C;
    const float* ip = in  + (size_t)blockIdx.z * mat;
    float*       op = out + (size_t)blockIdx.z * mat;
    const int c0 = blockIdx.x * 32;
    const int r0 = blockIdx.y * 32;
    const int tx = threadIdx.x & 31;
    const int ty = threadIdx.x >> 5;   // 0..7
#pragma unroll
    for (int s = 0; s < 4; s++)
        tile[ty + 8 * s][tx] = ip[(size_t)(r0 + ty + 8 * s) * C + c0 + tx];
    __syncthreads();
    const int pc = (tx & ~7) + p8(tx & 7);
#pragma unroll
    for (int s = 0; s < 4; s++)
        op[(size_t)(c0 + ty + 8 * s) * R + r0 + pc] = f2tff(tile[tx][ty + 8 * s]);
}

// ---------------- GEMM1: H = silu(X@W1) * (X@W2) ----------------
// grid (D_FF/BN=22, 144), 256 thr; warps 2(m) x 4(n), warp tile 64x32.
__global__ void __launch_bounds__(256)
gemm1_kernel() {
    const int mt = blockIdx.y;
    const int e  = g_tile_expert[mt];
    if (e < 0) return;
    const int nb   = blockIdx.x * BN;
    const int row0 = mt * BM;

    extern __shared__ float smem[];
    float* sA  = smem;                 // 2 * T_STAGE
    float* sB1 = sA  + 2 * T_STAGE;
    float* sB2 = sB1 + 2 * T_STAGE;

    const int tid  = threadIdx.x;
    const int lane = tid & 31;
    const int wid  = tid >> 5;
    const int wm   = wid >> 2;
    const int wn   = wid & 3;
    const int g    = lane >> 2;
    const int t    = lane & 3;

    // A loader: 4 tasks; q -> m = q>>3, granule kq = q&7 (positions, g_Xr pre-permuted)
    const float* apg[4];
    int av[4];
    uint32_t dA[4];
#pragma unroll
    for (int j = 0; j < 4; j++) {
        const int q = tid + 256 * j;
        const int m = q >> 3, kq = q & 7;
        const int tok = g_perm[row0 + m];
        av[j]  = (tok >= 0);
        apg[j] = g_Xr + (size_t)(tok < 0 ? 0 : tok) * D_MODEL + kq * 4;
        dA[j]  = smem_u32(sA + m * T_STRIDE + kq * 4);
    }
    // B loader ([n][k'] rows of transposed weights): q -> n = q>>3, kq = q&7
    const float* b1g[4];
    const float* b2g[4];
    uint32_t dBo[4];
#pragma unroll
    for (int j = 0; j < 4; j++) {
        const int q = tid + 256 * j;
        const int n = q >> 3, kq = q & 7;
        b1g[j] = g_W1t + (size_t)e * D_FF * D_MODEL + (size_t)(nb + n) * D_MODEL + kq * 4;
        b2g[j] = g_W2t + (size_t)e * D_FF * D_MODEL + (size_t)(nb + n) * D_MODEL + kq * 4;
        dBo[j] = (uint32_t)((n * T_STRIDE + kq * 4) * 4);
    }
    const uint32_t sB1u = smem_u32(sB1), sB2u = smem_u32(sB2);

    const int KT = D_MODEL / BK;   // 32

    auto issue = [&](int kt) {
        if (kt < KT) {
            const int s = kt & 1;
            const int kg = kt * BK;
            const uint32_t so = s * T_STAGE * 4;
#pragma unroll
            for (int j = 0; j < 4; j++)
                cp16_pred(dA[j] + so, apg[j] + kg, av[j]);
#pragma unroll
            for (int j = 0; j < 4; j++) {
                cp16(sB1u + dBo[j] + so, b1g[j] + kg);
                cp16(sB2u + dBo[j] + so, b2g[j] + kg);
            }
        }
        CP_COMMIT();
    };

    float accg[4][4][4] = {};
    float accv[4][4][4] = {};

    issue(0); issue(1);

    for (int kt = 0; kt < KT; kt++) {
        CP_WAIT1();
        __syncthreads();

        const int s = kt & 1;
        const float* As  = sA  + s * T_STAGE;
        const float* B1s = sB1 + s * T_STAGE;
        const float* B2s = sB2 + s * T_STAGE;

#pragma unroll
        for (int ks = 0; ks < 4; ks++) {
            const int kk = ks * 8 + 2 * t;
            uint32_t a[4][4];
#pragma unroll
            for (int mi = 0; mi < 4; mi++) {
                const int mr = wm * 64 + mi * 16;
                float2 v0 = *(const float2*)&As[(mr + g    ) * T_STRIDE + kk];
                float2 v1 = *(const float2*)&As[(mr + g + 8) * T_STRIDE + kk];
                a[mi][0] = __float_as_uint(v0.x);
                a[mi][1] = __float_as_uint(v1.x);
                a[mi][2] = __float_as_uint(v0.y);
                a[mi][3] = __float_as_uint(v1.y);
            }
#pragma unroll
            for (int ni = 0; ni < 4; ni++) {
                const int nc = wn * 32 + ni * 8 + g;
                float2 vb1 = *(const float2*)&B1s[nc * T_STRIDE + kk];
                float2 vb2 = *(const float2*)&B2s[nc * T_STRIDE + kk];
                uint32_t b1[2] = { __float_as_uint(vb1.x), __float_as_uint(vb1.y) };
                uint32_t b2[2] = { __float_as_uint(vb2.x), __float_as_uint(vb2.y) };
#pragma unroll
                for (int mi = 0; mi < 4; mi++) {
                    mma8(accg[mi][ni], a[mi], b1);
                    mma8(accv[mi][ni], a[mi], b2);
                }
            }
        }
        __syncthreads();
        issue(kt + 2);
    }

    // epilogue: SwiGLU -> g_H, tf32-rounded, stored k-interleaved.
    // orig col c = base + 2t (+1) maps to positions pos0 = (t<2 ? 4t : 4t-7), pos0+2.
    const int pos0 = (t < 2) ? 4 * t : 4 * t - 7;
#pragma unroll
    for (int mi = 0; mi < 4; mi++) {
        const int r = wm * 64 + mi * 16 + g;
        const size_t h0 = (size_t)(row0 + r)     * D_FF;
        const size_t h8 = (size_t)(row0 + r + 8) * D_FF;
#pragma unroll
        for (int ni = 0; ni < 4; ni++) {
            const int cb = nb + wn * 32 + ni * 8;
            g_H[h0 + cb + pos0    ] = f2tff(silu_f(accg[mi][ni][0]) * accv[mi][ni][0]);
            g_H[h0 + cb + pos0 + 2] = f2tff(silu_f(accg[mi][ni][1]) * accv[mi][ni][1]);
            g_H[h8 + cb + pos0    ] = f2tff(silu_f(accg[mi][ni][2]) * accv[mi][ni][2]);
            g_H[h8 + cb + pos0 + 2] = f2tff(silu_f(accg[mi][ni][3]) * accv[mi][ni][3]);
        }
    }
}

// ---------------- GEMM2: out += wgt * (H @ W3) ----------------
// grid (D_MODEL/BN=8, 144), 256 thr, 2 CTAs/SM.
__global__ void __launch_bounds__(256, 2)
gemm2_kernel(float* __restrict__ out) {
    const int mt = blockIdx.y;
    const int e  = g_tile_expert[mt];
    if (e < 0) return;
    const int nb   = blockIdx.x * BN;
    const int row0 = mt * BM;

    extern __shared__ float smem[];
    float* sA = smem;
    float* sB = sA + 2 * T_STAGE;

    const int tid  = threadIdx.x;
    const int lane = tid & 31;
    const int wid  = tid >> 5;
    const int wm   = wid >> 2;
    const int wn   = wid & 3;
    const int g    = lane >> 2;
    const int t    = lane & 3;

    const float* apg[4];
    uint32_t dA[4];
#pragma unroll
    for (int j = 0; j < 4; j++) {
        const int q = tid + 256 * j;
        const int m = q >> 3, kq = q & 7;
        apg[j] = g_H + (size_t)(row0 + m) * D_FF + kq * 4;
        dA[j]  = smem_u32(sA + m * T_STRIDE + kq * 4);
    }
    const float* bg[4];
    uint32_t dBo[4];
#pragma unroll
    for (int j = 0; j < 4; j++) {
        const int q = tid + 256 * j;
        const int n = q >> 3, kq = q & 7;
        bg[j]  = g_W3t + (size_t)e * D_MODEL * D_FF + (size_t)(nb + n) * D_FF + kq * 4;
        dBo[j] = (uint32_t)((n * T_STRIDE + kq * 4) * 4);
    }
    const uint32_t sBu = smem_u32(sB);

    const int KT = D_FF / BK;   // 88

    auto issue = [&](int kt) {
        if (kt < KT) {
            const int s = kt & 1;
            const int kg = kt * BK;
            const uint32_t so = s * T_STAGE * 4;
#pragma unroll
            for (int j = 0; j < 4; j++)
                cp16(dA[j] + so, apg[j] + kg);
#pragma unroll
            for (int j = 0; j < 4; j++)
                cp16(sBu + dBo[j] + so, bg[j] + kg);
        }
        CP_COMMIT();
    };

    float acc[4][4][4] = {};

    issue(0); issue(1);

    for (int kt = 0; kt < KT; kt++) {
        CP_WAIT1();
        __syncthreads();

        const int s = kt & 1;
        const float* As = sA + s * T_STAGE;
        const float* Bs = sB + s * T_STAGE;

#pragma unroll
        for (int ks = 0; ks < 4; ks++) {
            const int kk = ks * 8 + 2 * t;
            uint32_t a[4][4];
#pragma unroll
            for (int mi = 0; mi < 4; mi++) {
                const int mr = wm * 64 + mi * 16;
                float2 v0 = *(const float2*)&As[(mr + g    ) * T_STRIDE + kk];
                float2 v1 = *(const float2*)&As[(mr + g + 8) * T_STRIDE + kk];
                a[mi][0] = __float_as_uint(v0.x);
                a[mi][1] = __float_as_uint(v1.x);
                a[mi][2] = __float_as_uint(v0.y);
                a[mi][3] = __float_as_uint(v1.y);
            }
#pragma unroll
            for (int ni = 0; ni < 4; ni++) {
                const int nc = wn * 32 + ni * 8 + g;
                float2 vb = *(const float2*)&Bs[nc * T_STRIDE + kk];
                uint32_t b[2] = { __float_as_uint(vb.x), __float_as_uint(vb.y) };
#pragma unroll
                for (int mi = 0; mi < 4; mi++)
                    mma8(acc[mi][ni], a[mi], b);
            }
        }
        __syncthreads();
        issue(kt + 2);
    }

    // epilogue: weighted scatter-add (out is NOT permuted; exactly 2 adds/token)
#pragma unroll
    for (int mi = 0; mi < 4; mi++) {
        const int r  = wm * 64 + mi * 16 + g;
        const int s0 = row0 + r;
        const int s8 = s0 + 8;
        const int tk0 = g_perm[s0];
        const int tk8 = g_perm[s8];
        const float wt0 = (tk0 >= 0) ? g_wgt[s0] : 0.f;
        const float wt8 = (tk8 >= 0) ? g_wgt[s8] : 0.f;
#pragma unroll
        for (int ni = 0; ni < 4; ni++) {
            const int c = nb + wn * 32 + ni * 8 + 2 * t;
            if (tk0 >= 0) {
                atomicAdd(&out[(size_t)tk0 * D_MODEL + c    ], acc[mi][ni][0] * wt0);
                atomicAdd(&out[(size_t)tk0 * D_MODEL + c + 1], acc[mi][ni][1] * wt0);
            }
            if (tk8 >= 0) {
                atomicAdd(&out[(size_t)tk8 * D_MODEL + c    ], acc[mi][ni][2] * wt8);
                atomicAdd(&out[(size_t)tk8 * D_MODEL + c + 1], acc[mi][ni][3] * wt8);
            }
        }
    }
}

// ---------------- launch ----------------
extern "C" void kernel_launch(void* const* d_in, const int* in_sizes, int n_in,
                              void* d_out, int out_size) {
    const float* x    = (const float*)d_in[0];
    const int*   eidx = (const int*)  d_in[1];
    const float* ew   = (const float*)d_in[2];
    const float* w1   = (const float*)d_in[3];
    const float* w2   = (const float*)d_in[4];
    const float* w3   = (const float*)d_in[5];
    float* out = (float*)d_out;

    const int smem1 = 2 * T_STAGE * 3 * 4;   // 122880 B -> 1 CTA/SM
    const int smem2 = 2 * T_STAGE * 2 * 4;   //  81920 B -> 2 CTAs/SM
    static int attr_done = 0;
    if (!attr_done) {
        cudaFuncSetAttribute(gemm1_kernel, cudaFuncAttributeMaxDynamicSharedMemorySize, smem1);
        cudaFuncSetAttribute(gemm2_kernel, cudaFuncAttributeMaxDynamicSharedMemorySize, smem2);
        attr_done = 1;
    }

    float* w1t; cudaGetSymbolAddress((void**)&w1t, g_W1t);
    float* w2t; cudaGetSymbolAddress((void**)&w2t, g_W2t);
    float* w3t; cudaGetSymbolAddress((void**)&w3t, g_W3t);

    init_kernel<<<(MAX_SLOTS + 255) / 256, 256>>>();
    zero_out_kernel<<<(N_TOKENS * D_MODEL / 4 + 255) / 256, 256>>>((float4*)out);
    round_x_kernel<<<(N_TOKENS * D_MODEL / 8 + 255) / 256, 256>>>((const float4*)x);
    count_kernel<<<(A_TOTAL + 255) / 256, 256>>>(eidx);
    scan_kernel<<<1, 32>>>();
    scatter_kernel<<<(A_TOTAL + 255) / 256, 256>>>(eidx, ew);

    // w1,w2: [d=1024][f=2816] -> [f][d'] ; w3: [f=2816][d=1024] -> [d][f']
    transpose_round_kernel<<<dim3(D_FF / 32, D_MODEL / 32, N_EXPERTS), 256>>>(w1, w1t, D_MODEL, D_FF);
    transpose_round_kernel<<<dim3(D_FF / 32, D_MODEL / 32, N_EXPERTS), 256>>>(w2, w2t, D_MODEL, D_FF);
    transpose_round_kernel<<<dim3(D_MODEL / 32, D_FF / 32, N_EXPERTS), 256>>>(w3, w3t, D_FF, D_MODEL);

    gemm1_kernel<<<dim3(D_FF / BN, MAX_MTILES), 256, smem1>>>();
    gemm2_kernel<<<dim3(D_MODEL / BN, MAX_MTILES), 256, smem2>>>(out);
}

// round 6
// speedup vs baseline: 1.0291x; 1.0291x over previous
#include <cuda_runtime.h>
#include <cstdint>

#define N_EXPERTS 16
#define D_MODEL   1024
#define D_FF      2816
#define N_TOKENS  8192
#define TOP_K     2
#define A_TOTAL   (N_TOKENS * TOP_K)

#define BM 128
#define BK 16
#define BN 128
#define STAGES 4

#define A_ST 16                     // A smem row stride (floats): no pad, LDS.128 conflict-free
#define B_ST 136                    // B smem row stride: (8t+g) banks distinct
#define A_STAGE (BM * A_ST)         // 2048 floats
#define B_STAGE (BK * B_ST)         // 2176 floats

#define MAX_SLOTS  (A_TOTAL + N_EXPERTS * BM)  // 18432
#define MAX_MTILES (MAX_SLOTS / BM)            // 144

// ---------------- scratch (device globals) ----------------
__device__ int   g_perm[MAX_SLOTS];
__device__ float g_wgt[MAX_SLOTS];
__device__ int   g_counts[N_EXPERTS];
__device__ int   g_offsets[N_EXPERTS];
__device__ int   g_tile_expert[MAX_MTILES];
__device__ float g_Xr[(size_t)N_TOKENS * D_MODEL];   // tf32-rounded, 16-interleaved k
__device__ float g_H [(size_t)MAX_SLOTS * D_FF];     // tf32-rounded, 16-interleaved k

// ---------------- helpers ----------------
__device__ __forceinline__ uint32_t f2tf(float f) {
    uint32_t r;
    asm("cvt.rna.tf32.f32 %0, %1;" : "=r"(r) : "f"(f));
    return r;
}
__device__ __forceinline__ float f2tff(float f) { return __uint_as_float(f2tf(f)); }

__device__ __forceinline__ void mma8(float* c, const uint32_t* a, const uint32_t* b) {
    asm volatile(
        "mma.sync.aligned.m16n8k8.row.col.f32.tf32.tf32.f32 "
        "{%0,%1,%2,%3}, {%4,%5,%6,%7}, {%8,%9}, {%0,%1,%2,%3};\n"
        : "+f"(c[0]), "+f"(c[1]), "+f"(c[2]), "+f"(c[3])
        : "r"(a[0]), "r"(a[1]), "r"(a[2]), "r"(a[3]),
          "r"(b[0]), "r"(b[1]));
}
__device__ __forceinline__ float silu_f(float x) { return x / (1.0f + __expf(-x)); }
__device__ __forceinline__ uint32_t smem_u32(const void* p) {
    return (uint32_t)__cvta_generic_to_shared(p);
}
__device__ __forceinline__ void cp16(uint32_t dst, const void* src) {
    asm volatile("cp.async.cg.shared.global [%0], [%1], 16;" :: "r"(dst), "l"(src));
}
__device__ __forceinline__ void cp16_pred(uint32_t dst, const void* src, int valid) {
    int sz = valid ? 16 : 0;   // sz=0 zero-fills the 16B destination
    asm volatile("cp.async.cg.shared.global [%0], [%1], 16, %2;"
                 :: "r"(dst), "l"(src), "r"(sz));
}
#define CP_COMMIT() asm volatile("cp.async.commit_group;" ::: "memory")
#define CP_WAIT2()  asm volatile("cp.async.wait_group 2;"  ::: "memory")

// interleave position within a 16-block: orig k w -> pos 4*(w&3) + (w>>2)
__device__ __forceinline__ int ipos(int w) { return ((w & 3) << 2) + (w >> 2); }

// ---------------- dispatch ----------------
__global__ void init_kernel() {
    int i = blockIdx.x * blockDim.x + threadIdx.x;
    if (i < MAX_SLOTS) g_perm[i] = -1;
    if (i < N_EXPERTS) g_counts[i] = 0;
}
__global__ void zero_out_kernel(float4* __restrict__ out) {
    int i = blockIdx.x * blockDim.x + threadIdx.x;
    if (i < N_TOKENS * D_MODEL / 4) out[i] = make_float4(0.f, 0.f, 0.f, 0.f);
}
// round + 16-interleave x: out16[p] = tf32(in16[4*(p&3) + (p>>2)])
__global__ void round_x_kernel(const float4* __restrict__ x) {
    int i = blockIdx.x * blockDim.x + threadIdx.x;   // 16-float block index
    if (i < N_TOKENS * D_MODEL / 16) {
        float4 v[4];
#pragma unroll
        for (int j = 0; j < 4; j++) v[j] = x[4 * i + j];
        const float* vf = (const float*)v;
        uint4 o[4];
        uint32_t* of = (uint32_t*)o;
#pragma unroll
        for (int p = 0; p < 16; p++) of[p] = f2tf(vf[4 * (p & 3) + (p >> 2)]);
#pragma unroll
        for (int j = 0; j < 4; j++) *(uint4*)&g_Xr[(size_t)(4 * i + j) * 4] = o[j];
    }
}
__global__ void count_kernel(const int* __restrict__ eidx) {
    int i = blockIdx.x * blockDim.x + threadIdx.x;
    if (i < A_TOTAL) atomicAdd(&g_counts[eidx[i]], 1);
}
__global__ void scan_kernel() {
    if (threadIdx.x == 0 && blockIdx.x == 0) {
        for (int i = 0; i < MAX_MTILES; i++) g_tile_expert[i] = -1;
        int acc = 0;
        for (int e = 0; e < N_EXPERTS; e++) {
            g_offsets[e] = acc;
            int nt = (g_counts[e] + BM - 1) / BM;
            int t0 = acc / BM;
            for (int i = 0; i < nt; i++) g_tile_expert[t0 + i] = e;
            acc += nt * BM;
        }
    }
}
__global__ void scatter_kernel(const int* __restrict__ eidx,
                               const float* __restrict__ ew) {
    int i = blockIdx.x * blockDim.x + threadIdx.x;
    if (i < A_TOTAL) {
        int e = eidx[i];
        int p = atomicAdd(&g_offsets[e], 1);
        g_perm[p] = i / TOP_K;
        g_wgt[p]  = ew[i];
    }
}

// ---------------- GEMM1: H = silu(X@W1) * (X@W2) ----------------
// grid (D_FF/BN=22, 144), 256 thr; warps 2(m) x 4(n), warp tile 64x32.
__global__ void __launch_bounds__(256)
gemm1_kernel(const float* __restrict__ w1, const float* __restrict__ w2) {
    const int mt = blockIdx.y;
    const int e  = g_tile_expert[mt];
    if (e < 0) return;
    const int nb   = blockIdx.x * BN;
    const int row0 = mt * BM;

    extern __shared__ float smem[];
    float* sA  = smem;                     // STAGES * A_STAGE
    float* sB1 = sA  + STAGES * A_STAGE;   // STAGES * B_STAGE
    float* sB2 = sB1 + STAGES * B_STAGE;

    const int tid  = threadIdx.x;
    const int lane = tid & 31;
    const int wid  = tid >> 5;
    const int wm   = wid >> 2;      // 0..1
    const int wn   = wid & 3;       // 0..3
    const int g    = lane >> 2;
    const int t    = lane & 3;

    // A loader: 2 tasks; q = tid + 256j -> m = q>>2 (0..127), quad kq = q&3
    const float* apg[2];
    int av[2];
    uint32_t dA[2];
#pragma unroll
    for (int j = 0; j < 2; j++) {
        const int q = tid + 256 * j;
        const int m = q >> 2, kq = q & 3;
        const int tok = g_perm[row0 + m];
        av[j]  = (tok >= 0);
        apg[j] = g_Xr + (size_t)(tok < 0 ? 0 : tok) * D_MODEL + kq * 4;
        dA[j]  = smem_u32(sA + m * A_ST + kq * 4);
    }
    // B loader: 2 tasks per matrix; q -> k = q>>5 (0..15), quad nq = q&31
    const float* b1g[2];
    const float* b2g[2];
    uint32_t dB1[2], dB2[2];
#pragma unroll
    for (int j = 0; j < 2; j++) {
        const int q = tid + 256 * j;
        const int k = q >> 5, nq = q & 31;
        b1g[j] = w1 + (size_t)e * D_MODEL * D_FF + (size_t)k * D_FF + nb + nq * 4;
        b2g[j] = w2 + (size_t)e * D_MODEL * D_FF + (size_t)k * D_FF + nb + nq * 4;
        dB1[j] = smem_u32(sB1 + k * B_ST + nq * 4);
        dB2[j] = smem_u32(sB2 + k * B_ST + nq * 4);
    }

    const int KT = D_MODEL / BK;   // 64

    auto issue = [&](int kt) {
        if (kt < KT) {
            const int s = kt & (STAGES - 1);
            const int kg = kt * BK;
#pragma unroll
            for (int j = 0; j < 2; j++)
                cp16_pred(dA[j] + s * A_STAGE * 4, apg[j] + kg, av[j]);
#pragma unroll
            for (int j = 0; j < 2; j++) {
                cp16(dB1[j] + s * B_STAGE * 4, b1g[j] + (size_t)kg * D_FF);
                cp16(dB2[j] + s * B_STAGE * 4, b2g[j] + (size_t)kg * D_FF);
            }
        }
        CP_COMMIT();
    };

    float accg[4][4][4] = {};
    float accv[4][4][4] = {};

    issue(0); issue(1); issue(2);

    for (int kt = 0; kt < KT; kt++) {
        CP_WAIT2();
        __syncthreads();
        issue(kt + 3);   // writes stage (kt-1)&3; all warps past sync -> safe

        const int s = kt & (STAGES - 1);
        const float* As  = sA  + s * A_STAGE;
        const float* B1s = sB1 + s * B_STAGE;
        const float* B2s = sB2 + s * B_STAGE;

        // A fragments: one LDS.128 per (mi, row-half) covers k = t,t+4,t+8,t+12
        uint4 A0[4], A1[4];
#pragma unroll
        for (int mi = 0; mi < 4; mi++) {
            const int mr = wm * 64 + mi * 16;
            A0[mi] = *(const uint4*)&As[(mr + g    ) * A_ST + 4 * t];
            A1[mi] = *(const uint4*)&As[(mr + g + 8) * A_ST + 4 * t];
        }
#pragma unroll
        for (int ks = 0; ks < 2; ks++) {
            const int kk = ks * 8;
            uint32_t a[4][4];
#pragma unroll
            for (int mi = 0; mi < 4; mi++) {
                a[mi][0] = ks ? A0[mi].z : A0[mi].x;
                a[mi][1] = ks ? A1[mi].z : A1[mi].x;
                a[mi][2] = ks ? A0[mi].w : A0[mi].y;
                a[mi][3] = ks ? A1[mi].w : A1[mi].y;
            }
#pragma unroll
            for (int ni = 0; ni < 4; ni++) {
                const int nc = wn * 32 + ni * 8 + g;
                uint32_t b1[2], b2[2];
                b1[0] = f2tf(B1s[(kk + t    ) * B_ST + nc]);
                b1[1] = f2tf(B1s[(kk + t + 4) * B_ST + nc]);
                b2[0] = f2tf(B2s[(kk + t    ) * B_ST + nc]);
                b2[1] = f2tf(B2s[(kk + t + 4) * B_ST + nc]);
#pragma unroll
                for (int mi = 0; mi < 4; mi++) {
                    mma8(accg[mi][ni], a[mi], b1);
                    mma8(accv[mi][ni], a[mi], b2);
                }
            }
        }
    }

    // epilogue: SwiGLU -> g_H, tf32-rounded, 16-interleaved along f
#pragma unroll
    for (int mi = 0; mi < 4; mi++) {
        const int r = wm * 64 + mi * 16 + g;
        const size_t h0 = (size_t)(row0 + r)     * D_FF;
        const size_t h8 = (size_t)(row0 + r + 8) * D_FF;
#pragma unroll
        for (int ni = 0; ni < 4; ni++) {
            const int c  = nb + wn * 32 + ni * 8 + 2 * t;
            const int cb = c & ~15;
            const int p0 = cb + ipos(c & 15);
            const int p1 = cb + ipos((c + 1) & 15);
            g_H[h0 + p0] = f2tff(silu_f(accg[mi][ni][0]) * accv[mi][ni][0]);
            g_H[h0 + p1] = f2tff(silu_f(accg[mi][ni][1]) * accv[mi][ni][1]);
            g_H[h8 + p0] = f2tff(silu_f(accg[mi][ni][2]) * accv[mi][ni][2]);
            g_H[h8 + p1] = f2tff(silu_f(accg[mi][ni][3]) * accv[mi][ni][3]);
        }
    }
}

// ---------------- GEMM2: out += wgt * (H @ W3) ----------------
// grid (D_MODEL/BN=8, 144), 256 thr, 2 CTAs/SM.
__global__ void __launch_bounds__(256, 2)
gemm2_kernel(const float* __restrict__ w3, float* __restrict__ out) {
    const int mt = blockIdx.y;
    const int e  = g_tile_expert[mt];
    if (e < 0) return;
    const int nb   = blockIdx.x * BN;
    const int row0 = mt * BM;

    extern __shared__ float smem[];
    float* sA = smem;
    float* sB = sA + STAGES * A_STAGE;

    const int tid  = threadIdx.x;
    const int lane = tid & 31;
    const int wid  = tid >> 5;
    const int wm   = wid >> 2;
    const int wn   = wid & 3;
    const int g    = lane >> 2;
    const int t    = lane & 3;

    const float* apg[2];
    uint32_t dA[2];
#pragma unroll
    for (int j = 0; j < 2; j++) {
        const int q = tid + 256 * j;
        const int m = q >> 2, kq = q & 3;
        apg[j] = g_H + (size_t)(row0 + m) * D_FF + kq * 4;   // pad rows are zero
        dA[j]  = smem_u32(sA + m * A_ST + kq * 4);
    }
    const float* bg[2];
    uint32_t dB[2];
#pragma unroll
    for (int j = 0; j < 2; j++) {
        const int q = tid + 256 * j;
        const int k = q >> 5, nq = q & 31;
        bg[j] = w3 + (size_t)e * D_FF * D_MODEL + (size_t)k * D_MODEL + nb + nq * 4;
        dB[j] = smem_u32(sB + k * B_ST + nq * 4);
    }

    const int KT = D_FF / BK;   // 176

    auto issue = [&](int kt) {
        if (kt < KT) {
            const int s = kt & (STAGES - 1);
            const int kg = kt * BK;
#pragma unroll
            for (int j = 0; j < 2; j++)
                cp16(dA[j] + s * A_STAGE * 4, apg[j] + kg);
#pragma unroll
            for (int j = 0; j < 2; j++)
                cp16(dB[j] + s * B_STAGE * 4, bg[j] + (size_t)kg * D_MODEL);
        }
        CP_COMMIT();
    };

    float acc[4][4][4] = {};

    issue(0); issue(1); issue(2);

    for (int kt = 0; kt < KT; kt++) {
        CP_WAIT2();
        __syncthreads();
        issue(kt + 3);

        const int s = kt & (STAGES - 1);
        const float* As = sA + s * A_STAGE;
        const float* Bs = sB + s * B_STAGE;

        uint4 A0[4], A1[4];
#pragma unroll
        for (int mi = 0; mi < 4; mi++) {
            const int mr = wm * 64 + mi * 16;
            A0[mi] = *(const uint4*)&As[(mr + g    ) * A_ST + 4 * t];
            A1[mi] = *(const uint4*)&As[(mr + g + 8) * A_ST + 4 * t];
        }
#pragma unroll
        for (int ks = 0; ks < 2; ks++) {
            const int kk = ks * 8;
            uint32_t a[4][4];
#pragma unroll
            for (int mi = 0; mi < 4; mi++) {
                a[mi][0] = ks ? A0[mi].z : A0[mi].x;
                a[mi][1] = ks ? A1[mi].z : A1[mi].x;
                a[mi][2] = ks ? A0[mi].w : A0[mi].y;
                a[mi][3] = ks ? A1[mi].w : A1[mi].y;
            }
#pragma unroll
            for (int ni = 0; ni < 4; ni++) {
                const int nc = wn * 32 + ni * 8 + g;
                uint32_t b[2];
                b[0] = f2tf(Bs[(kk + t    ) * B_ST + nc]);
                b[1] = f2tf(Bs[(kk + t + 4) * B_ST + nc]);
#pragma unroll
                for (int mi = 0; mi < 4; mi++)
                    mma8(acc[mi][ni], a[mi], b);
            }
        }
    }

    // epilogue: weighted scatter-add (out not permuted; exactly 2 adds/token)
#pragma unroll
    for (int mi = 0; mi < 4; mi++) {
        const int r  = wm * 64 + mi * 16 + g;
        const int s0 = row0 + r;
        const int s8 = s0 + 8;
        const int tk0 = g_perm[s0];
        const int tk8 = g_perm[s8];
        const float wt0 = (tk0 >= 0) ? g_wgt[s0] : 0.f;
        const float wt8 = (tk8 >= 0) ? g_wgt[s8] : 0.f;
#pragma unroll
        for (int ni = 0; ni < 4; ni++) {
            const int c = nb + wn * 32 + ni * 8 + 2 * t;
            if (tk0 >= 0) {
                atomicAdd(&out[(size_t)tk0 * D_MODEL + c    ], acc[mi][ni][0] * wt0);
                atomicAdd(&out[(size_t)tk0 * D_MODEL + c + 1], acc[mi][ni][1] * wt0);
            }
            if (tk8 >= 0) {
                atomicAdd(&out[(size_t)tk8 * D_MODEL + c    ], acc[mi][ni][2] * wt8);
                atomicAdd(&out[(size_t)tk8 * D_MODEL + c + 1], acc[mi][ni][3] * wt8);
            }
        }
    }
}

// ---------------- launch ----------------
extern "C" void kernel_launch(void* const* d_in, const int* in_sizes, int n_in,
                              void* d_out, int out_size) {
    const float* x    = (const float*)d_in[0];
    const int*   eidx = (const int*)  d_in[1];
    const float* ew   = (const float*)d_in[2];
    const float* w1   = (const float*)d_in[3];
    const float* w2   = (const float*)d_in[4];
    const float* w3   = (const float*)d_in[5];
    float* out = (float*)d_out;

    const int smem1 = STAGES * (A_STAGE + 2 * B_STAGE) * 4;   // 102400 B
    const int smem2 = STAGES * (A_STAGE + B_STAGE) * 4;       //  67584 B
    static int attr_done = 0;
    if (!attr_done) {
        cudaFuncSetAttribute(gemm1_kernel, cudaFuncAttributeMaxDynamicSharedMemorySize, smem1);
        cudaFuncSetAttribute(gemm2_kernel, cudaFuncAttributeMaxDynamicSharedMemorySize, smem2);
        attr_done = 1;
    }

    init_kernel<<<(MAX_SLOTS + 255) / 256, 256>>>();
    zero_out_kernel<<<(N_TOKENS * D_MODEL / 4 + 255) / 256, 256>>>((float4*)out);
    round_x_kernel<<<(N_TOKENS * D_MODEL / 16 + 255) / 256, 256>>>((const float4*)x);
    count_kernel<<<(A_TOTAL + 255) / 256, 256>>>(eidx);
    scan_kernel<<<1, 32>>>();
    scatter_kernel<<<(A_TOTAL + 255) / 256, 256>>>(eidx, ew);

    gemm1_kernel<<<dim3(D_FF / BN, MAX_MTILES), 256, smem1>>>(w1, w2);
    gemm2_kernel<<<dim3(D_MODEL / BN, MAX_MTILES), 256, smem2>>>(w3, out);
}

// round 7
// speedup vs baseline: 1.0632x; 1.0331x over previous
#include <cuda_runtime.h>
#include <cstdint>

#define N_EXPERTS 16
#define D_MODEL   1024
#define D_FF      2816
#define N_TOKENS  8192
#define TOP_K     2
#define A_TOTAL   (N_TOKENS * TOP_K)

#define BM 128
#define BK 32
#define BN 128

#define A_ST 48                     // A smem row stride (floats): LDS.128 conflict-free
#define B_ST 136                    // B smem row stride: (8t+g) banks distinct
#define A_STAGE (BM * A_ST)         // 6144 floats
#define B_STAGE (BK * B_ST)         // 4352 floats

#define MAX_SLOTS  (A_TOTAL + N_EXPERTS * BM)  // 18432
#define MAX_MTILES (MAX_SLOTS / BM)            // 144

// ---------------- scratch (device globals) ----------------
__device__ int   g_perm[MAX_SLOTS];
__device__ float g_wgt[MAX_SLOTS];
__device__ int   g_counts[N_EXPERTS];
__device__ int   g_offsets[N_EXPERTS];
__device__ int   g_tile_expert[MAX_MTILES];
__device__ float g_Xr[(size_t)N_TOKENS * D_MODEL];   // tf32-rounded, 16-interleaved k
__device__ float g_H [(size_t)MAX_SLOTS * D_FF];     // tf32-rounded, 16-interleaved k

// ---------------- helpers ----------------
__device__ __forceinline__ uint32_t f2tf(float f) {
    uint32_t r;
    asm("cvt.rna.tf32.f32 %0, %1;" : "=r"(r) : "f"(f));
    return r;
}
__device__ __forceinline__ float f2tff(float f) { return __uint_as_float(f2tf(f)); }

__device__ __forceinline__ void mma8(float* c, const uint32_t* a, const uint32_t* b) {
    asm volatile(
        "mma.sync.aligned.m16n8k8.row.col.f32.tf32.tf32.f32 "
        "{%0,%1,%2,%3}, {%4,%5,%6,%7}, {%8,%9}, {%0,%1,%2,%3};\n"
        : "+f"(c[0]), "+f"(c[1]), "+f"(c[2]), "+f"(c[3])
        : "r"(a[0]), "r"(a[1]), "r"(a[2]), "r"(a[3]),
          "r"(b[0]), "r"(b[1]));
}
__device__ __forceinline__ float silu_f(float x) { return x / (1.0f + __expf(-x)); }
__device__ __forceinline__ uint32_t smem_u32(const void* p) {
    return (uint32_t)__cvta_generic_to_shared(p);
}
__device__ __forceinline__ void cp16(uint32_t dst, const void* src) {
    asm volatile("cp.async.cg.shared.global [%0], [%1], 16;" :: "r"(dst), "l"(src));
}
__device__ __forceinline__ void cp16_pred(uint32_t dst, const void* src, int valid) {
    int sz = valid ? 16 : 0;   // sz=0 zero-fills the 16B destination
    asm volatile("cp.async.cg.shared.global [%0], [%1], 16, %2;"
                 :: "r"(dst), "l"(src), "r"(sz));
}
#define CP_COMMIT() asm volatile("cp.async.commit_group;" ::: "memory")
#define CP_WAIT1()  asm volatile("cp.async.wait_group 1;"  ::: "memory")

// interleave position within a 16-block: orig k w -> pos 4*(w&3) + (w>>2)
__device__ __forceinline__ int ipos(int w) { return ((w & 3) << 2) + (w >> 2); }

// ---------------- dispatch ----------------
__global__ void init_kernel() {
    int i = blockIdx.x * blockDim.x + threadIdx.x;
    if (i < MAX_SLOTS) g_perm[i] = -1;
    if (i < N_EXPERTS) g_counts[i] = 0;
}
__global__ void zero_out_kernel(float4* __restrict__ out) {
    int i = blockIdx.x * blockDim.x + threadIdx.x;
    if (i < N_TOKENS * D_MODEL / 4) out[i] = make_float4(0.f, 0.f, 0.f, 0.f);
}
// round + 16-interleave x: out16[p] = tf32(in16[4*(p&3) + (p>>2)])
__global__ void round_x_kernel(const float4* __restrict__ x) {
    int i = blockIdx.x * blockDim.x + threadIdx.x;   // 16-float block index
    if (i < N_TOKENS * D_MODEL / 16) {
        float4 v[4];
#pragma unroll
        for (int j = 0; j < 4; j++) v[j] = x[4 * i + j];
        const float* vf = (const float*)v;
        uint4 o[4];
        uint32_t* of = (uint32_t*)o;
#pragma unroll
        for (int p = 0; p < 16; p++) of[p] = f2tf(vf[4 * (p & 3) + (p >> 2)]);
#pragma unroll
        for (int j = 0; j < 4; j++) *(uint4*)&g_Xr[(size_t)(4 * i + j) * 4] = o[j];
    }
}
__global__ void count_kernel(const int* __restrict__ eidx) {
    int i = blockIdx.x * blockDim.x + threadIdx.x;
    if (i < A_TOTAL) atomicAdd(&g_counts[eidx[i]], 1);
}
__global__ void scan_kernel() {
    if (threadIdx.x == 0 && blockIdx.x == 0) {
        for (int i = 0; i < MAX_MTILES; i++) g_tile_expert[i] = -1;
        int acc = 0;
        for (int e = 0; e < N_EXPERTS; e++) {
            g_offsets[e] = acc;
            int nt = (g_counts[e] + BM - 1) / BM;
            int t0 = acc / BM;
            for (int i = 0; i < nt; i++) g_tile_expert[t0 + i] = e;
            acc += nt * BM;
        }
    }
}
__global__ void scatter_kernel(const int* __restrict__ eidx,
                               const float* __restrict__ ew) {
    int i = blockIdx.x * blockDim.x + threadIdx.x;
    if (i < A_TOTAL) {
        int e = eidx[i];
        int p = atomicAdd(&g_offsets[e], 1);
        g_perm[p] = i / TOP_K;
        g_wgt[p]  = ew[i];
    }
}

// A-fragment extraction: uint4 at float-offset 4t of a 16-block holds k = {t, t+4, t+8, t+12}
// ks 0: (.x,.y) = k t, t+4 ; ks 1: (.z,.w) = k t+8, t+12
#define A_FRAG(a, V0, V1, hi) do {            \
    a[0] = hi ? (V0).z : (V0).x;              \
    a[1] = hi ? (V1).z : (V1).x;              \
    a[2] = hi ? (V0).w : (V0).y;              \
    a[3] = hi ? (V1).w : (V1).y;              \
} while (0)

// ---------------- GEMM1: H = silu(X@W1) * (X@W2) ----------------
// grid (D_FF/BN=22, 144), 256 thr; warps 2(m) x 4(n), warp tile 64x32.
// 3-stage cp.async pipeline, one __syncthreads per kt.
__global__ void __launch_bounds__(256)
gemm1_kernel(const float* __restrict__ w1, const float* __restrict__ w2) {
    const int mt = blockIdx.y;
    const int e  = g_tile_expert[mt];
    if (e < 0) return;
    const int nb   = blockIdx.x * BN;
    const int row0 = mt * BM;

    extern __shared__ float smem[];
    float* sA  = smem;                  // 3 * A_STAGE
    float* sB1 = sA  + 3 * A_STAGE;     // 3 * B_STAGE
    float* sB2 = sB1 + 3 * B_STAGE;

    const int tid  = threadIdx.x;
    const int lane = tid & 31;
    const int wid  = tid >> 5;
    const int wm   = wid >> 2;      // 0..1
    const int wn   = wid & 3;       // 0..3
    const int g    = lane >> 2;
    const int t    = lane & 3;

    // A loader: 4 tasks; q = tid + 256j -> m = q>>3 (0..127), quad kq = q&7
    const float* apg[4];
    int av[4];
    uint32_t dA[4];
#pragma unroll
    for (int j = 0; j < 4; j++) {
        const int q = tid + 256 * j;
        const int m = q >> 3, kq = q & 7;
        const int tok = g_perm[row0 + m];
        av[j]  = (tok >= 0);
        apg[j] = g_Xr + (size_t)(tok < 0 ? 0 : tok) * D_MODEL + kq * 4;
        dA[j]  = smem_u32(sA + m * A_ST + kq * 4);
    }
    // B loader: 4 tasks per matrix; q -> k = q>>5 (0..31), quad nq = q&31
    const float* b1g[4];
    const float* b2g[4];
    uint32_t dB1[4], dB2[4];
#pragma unroll
    for (int j = 0; j < 4; j++) {
        const int q = tid + 256 * j;
        const int k = q >> 5, nq = q & 31;
        b1g[j] = w1 + (size_t)e * D_MODEL * D_FF + (size_t)k * D_FF + nb + nq * 4;
        b2g[j] = w2 + (size_t)e * D_MODEL * D_FF + (size_t)k * D_FF + nb + nq * 4;
        dB1[j] = smem_u32(sB1 + k * B_ST + nq * 4);
        dB2[j] = smem_u32(sB2 + k * B_ST + nq * 4);
    }

    const int KT = D_MODEL / BK;   // 32

    auto issue = [&](int kt) {
        if (kt < KT) {
            const int s = kt % 3;
            const int kg = kt * BK;
#pragma unroll
            for (int j = 0; j < 4; j++)
                cp16_pred(dA[j] + s * A_STAGE * 4, apg[j] + kg, av[j]);
#pragma unroll
            for (int j = 0; j < 4; j++) {
                cp16(dB1[j] + s * B_STAGE * 4, b1g[j] + (size_t)kg * D_FF);
                cp16(dB2[j] + s * B_STAGE * 4, b2g[j] + (size_t)kg * D_FF);
            }
        }
        CP_COMMIT();
    };

    float accg[4][4][4] = {};
    float accv[4][4][4] = {};

    issue(0); issue(1);

    for (int kt = 0; kt < KT; kt++) {
        CP_WAIT1();
        __syncthreads();
        issue(kt + 2);   // writes stage (kt+2)%3 = (kt-1)%3: everyone done reading it

        const int s = kt % 3;
        const float* As  = sA  + s * A_STAGE;
        const float* B1s = sB1 + s * B_STAGE;
        const float* B2s = sB2 + s * B_STAGE;

        // A fragments: 2 LDS.128 per (mi): 16-blocks b=0 (k 0..15) and b=1 (k 16..31)
        uint4 A0[4][2], A1[4][2];
#pragma unroll
        for (int mi = 0; mi < 4; mi++) {
            const int mr = wm * 64 + mi * 16;
#pragma unroll
            for (int b = 0; b < 2; b++) {
                A0[mi][b] = *(const uint4*)&As[(mr + g    ) * A_ST + 16 * b + 4 * t];
                A1[mi][b] = *(const uint4*)&As[(mr + g + 8) * A_ST + 16 * b + 4 * t];
            }
        }
#pragma unroll
        for (int ks = 0; ks < 4; ks++) {
            const int kk = ks * 8;
            const int b  = ks >> 1, hi = ks & 1;
            uint32_t a[4][4];
#pragma unroll
            for (int mi = 0; mi < 4; mi++)
                A_FRAG(a[mi], A0[mi][b], A1[mi][b], hi);
#pragma unroll
            for (int ni = 0; ni < 4; ni++) {
                const int nc = wn * 32 + ni * 8 + g;
                uint32_t b1[2], b2[2];
                b1[0] = f2tf(B1s[(kk + t    ) * B_ST + nc]);
                b1[1] = f2tf(B1s[(kk + t + 4) * B_ST + nc]);
                b2[0] = f2tf(B2s[(kk + t    ) * B_ST + nc]);
                b2[1] = f2tf(B2s[(kk + t + 4) * B_ST + nc]);
#pragma unroll
                for (int mi = 0; mi < 4; mi++) {
                    mma8(accg[mi][ni], a[mi], b1);
                    mma8(accv[mi][ni], a[mi], b2);
                }
            }
        }
    }

    // epilogue: SwiGLU -> g_H, tf32-rounded, 16-interleaved along f
#pragma unroll
    for (int mi = 0; mi < 4; mi++) {
        const int r = wm * 64 + mi * 16 + g;
        const size_t h0 = (size_t)(row0 + r)     * D_FF;
        const size_t h8 = (size_t)(row0 + r + 8) * D_FF;
#pragma unroll
        for (int ni = 0; ni < 4; ni++) {
            const int c  = nb + wn * 32 + ni * 8 + 2 * t;
            const int cb = c & ~15;
            const int p0 = cb + ipos(c & 15);
            const int p1 = cb + ipos((c + 1) & 15);
            g_H[h0 + p0] = f2tff(silu_f(accg[mi][ni][0]) * accv[mi][ni][0]);
            g_H[h0 + p1] = f2tff(silu_f(accg[mi][ni][1]) * accv[mi][ni][1]);
            g_H[h8 + p0] = f2tff(silu_f(accg[mi][ni][2]) * accv[mi][ni][2]);
            g_H[h8 + p1] = f2tff(silu_f(accg[mi][ni][3]) * accv[mi][ni][3]);
        }
    }
}

// ---------------- GEMM2: out += wgt * (H @ W3) ----------------
// grid (D_MODEL/BN=8, 144), 256 thr, 2 CTAs/SM; 2-stage pipeline (R4 schedule).
__global__ void __launch_bounds__(256, 2)
gemm2_kernel(const float* __restrict__ w3, float* __restrict__ out) {
    const int mt = blockIdx.y;
    const int e  = g_tile_expert[mt];
    if (e < 0) return;
    const int nb   = blockIdx.x * BN;
    const int row0 = mt * BM;

    extern __shared__ float smem[];
    float* sA = smem;                  // 2 * A_STAGE
    float* sB = sA + 2 * A_STAGE;      // 2 * B_STAGE

    const int tid  = threadIdx.x;
    const int lane = tid & 31;
    const int wid  = tid >> 5;
    const int wm   = wid >> 2;
    const int wn   = wid & 3;
    const int g    = lane >> 2;
    const int t    = lane & 3;

    const float* apg[4];
    uint32_t dA[4];
#pragma unroll
    for (int j = 0; j < 4; j++) {
        const int q = tid + 256 * j;
        const int m = q >> 3, kq = q & 7;
        apg[j] = g_H + (size_t)(row0 + m) * D_FF + kq * 4;   // pad rows are zero
        dA[j]  = smem_u32(sA + m * A_ST + kq * 4);
    }
    const float* bg[4];
    uint32_t dB[4];
#pragma unroll
    for (int j = 0; j < 4; j++) {
        const int q = tid + 256 * j;
        const int k = q >> 5, nq = q & 31;
        bg[j] = w3 + (size_t)e * D_FF * D_MODEL + (size_t)k * D_MODEL + nb + nq * 4;
        dB[j] = smem_u32(sB + k * B_ST + nq * 4);
    }

    const int KT = D_FF / BK;   // 88

    auto issue = [&](int kt) {
        if (kt < KT) {
            const int s = kt & 1;
            const int kg = kt * BK;
#pragma unroll
            for (int j = 0; j < 4; j++)
                cp16(dA[j] + s * A_STAGE * 4, apg[j] + kg);
#pragma unroll
            for (int j = 0; j < 4; j++)
                cp16(dB[j] + s * B_STAGE * 4, bg[j] + (size_t)kg * D_MODEL);
        }
        CP_COMMIT();
    };

    float acc[4][4][4] = {};

    issue(0); issue(1);

    for (int kt = 0; kt < KT; kt++) {
        CP_WAIT1();
        __syncthreads();

        const int s = kt & 1;
        const float* As = sA + s * A_STAGE;
        const float* Bs = sB + s * B_STAGE;

        uint4 A0[4][2], A1[4][2];
#pragma unroll
        for (int mi = 0; mi < 4; mi++) {
            const int mr = wm * 64 + mi * 16;
#pragma unroll
            for (int b = 0; b < 2; b++) {
                A0[mi][b] = *(const uint4*)&As[(mr + g    ) * A_ST + 16 * b + 4 * t];
                A1[mi][b] = *(const uint4*)&As[(mr + g + 8) * A_ST + 16 * b + 4 * t];
            }
        }
#pragma unroll
        for (int ks = 0; ks < 4; ks++) {
            const int kk = ks * 8;
            const int b  = ks >> 1, hi = ks & 1;
            uint32_t a[4][4];
#pragma unroll
            for (int mi = 0; mi < 4; mi++)
                A_FRAG(a[mi], A0[mi][b], A1[mi][b], hi);
#pragma unroll
            for (int ni = 0; ni < 4; ni++) {
                const int nc = wn * 32 + ni * 8 + g;
                uint32_t b2[2];
                b2[0] = f2tf(Bs[(kk + t    ) * B_ST + nc]);
                b2[1] = f2tf(Bs[(kk + t + 4) * B_ST + nc]);
#pragma unroll
                for (int mi = 0; mi < 4; mi++)
                    mma8(acc[mi][ni], a[mi], b2);
            }
        }
        __syncthreads();
        issue(kt + 2);
    }

    // epilogue: weighted scatter-add (out not permuted; exactly 2 adds/token)
#pragma unroll
    for (int mi = 0; mi < 4; mi++) {
        const int r  = wm * 64 + mi * 16 + g;
        const int s0 = row0 + r;
        const int s8 = s0 + 8;
        const int tk0 = g_perm[s0];
        const int tk8 = g_perm[s8];
        const float wt0 = (tk0 >= 0) ? g_wgt[s0] : 0.f;
        const float wt8 = (tk8 >= 0) ? g_wgt[s8] : 0.f;
#pragma unroll
        for (int ni = 0; ni < 4; ni++) {
            const int c = nb + wn * 32 + ni * 8 + 2 * t;
            if (tk0 >= 0) {
                atomicAdd(&out[(size_t)tk0 * D_MODEL + c    ], acc[mi][ni][0] * wt0);
                atomicAdd(&out[(size_t)tk0 * D_MODEL + c + 1], acc[mi][ni][1] * wt0);
            }
            if (tk8 >= 0) {
                atomicAdd(&out[(size_t)tk8 * D_MODEL + c    ], acc[mi][ni][2] * wt8);
                atomicAdd(&out[(size_t)tk8 * D_MODEL + c + 1], acc[mi][ni][3] * wt8);
            }
        }
    }
}

// ---------------- launch ----------------
extern "C" void kernel_launch(void* const* d_in, const int* in_sizes, int n_in,
                              void* d_out, int out_size) {
    const float* x    = (const float*)d_in[0];
    const int*   eidx = (const int*)  d_in[1];
    const float* ew   = (const float*)d_in[2];
    const float* w1   = (const float*)d_in[3];
    const float* w2   = (const float*)d_in[4];
    const float* w3   = (const float*)d_in[5];
    float* out = (float*)d_out;

    const int smem1 = 3 * (A_STAGE + 2 * B_STAGE) * 4;   // 178176 B -> 1 CTA/SM
    const int smem2 = 2 * (A_STAGE + B_STAGE) * 4;       //  83968 B -> 2 CTAs/SM
    static int attr_done = 0;
    if (!attr_done) {
        cudaFuncSetAttribute(gemm1_kernel, cudaFuncAttributeMaxDynamicSharedMemorySize, smem1);
        cudaFuncSetAttribute(gemm2_kernel, cudaFuncAttributeMaxDynamicSharedMemorySize, smem2);
        attr_done = 1;
    }

    init_kernel<<<(MAX_SLOTS + 255) / 256, 256>>>();
    zero_out_kernel<<<(N_TOKENS * D_MODEL / 4 + 255) / 256, 256>>>((float4*)out);
    round_x_kernel<<<(N_TOKENS * D_MODEL / 16 + 255) / 256, 256>>>((const float4*)x);
    count_kernel<<<(A_TOTAL + 255) / 256, 256>>>(eidx);
    scan_kernel<<<1, 32>>>();
    scatter_kernel<<<(A_TOTAL + 255) / 256, 256>>>(eidx, ew);

    gemm1_kernel<<<dim3(D_FF / BN, MAX_MTILES), 256, smem1>>>(w1, w2);
    gemm2_kernel<<<dim3(D_MODEL / BN, MAX_MTILES), 256, smem2>>>(w3, out);
}

// round 8
// speedup vs baseline: 1.1681x; 1.0987x over previous
#include <cuda_runtime.h>
#include <cstdint>

#define N_EXPERTS 16
#define D_MODEL   1024
#define D_FF      2816
#define N_TOKENS  8192
#define TOP_K     2
#define A_TOTAL   (N_TOKENS * TOP_K)

#define BM 128
#define BK 32
#define BN 128

#define A_STRIDE 36      // [m][k] row stride: bank (4g+t)%32 distinct -> conflict-free frags
#define B_STRIDE 136     // [k][n] row stride: bank (8t+g)%32 distinct -> conflict-free frags
#define A_STAGE (BM * A_STRIDE)   // 4608 floats
#define B_STAGE (BK * B_STRIDE)   // 4352 floats

#define MAX_SLOTS  (A_TOTAL + N_EXPERTS * BM)  // 18432
#define MAX_MTILES (MAX_SLOTS / BM)            // 144

// ---------------- scratch ----------------
__device__ int   g_perm[MAX_SLOTS];
__device__ float g_wgt[MAX_SLOTS];
__device__ int   g_offsets[N_EXPERTS];
__device__ int   g_tile_expert[MAX_MTILES];
__device__ float g_Xr[(size_t)N_TOKENS * D_MODEL];   // tf32-pre-rounded x
__device__ float g_H[(size_t)MAX_SLOTS * D_FF];      // SwiGLU activations (tf32-rounded)

// ---------------- helpers ----------------
__device__ __forceinline__ uint32_t f2tf(float f) {
    uint32_t r;
    asm("cvt.rna.tf32.f32 %0, %1;" : "=r"(r) : "f"(f));
    return r;
}
__device__ __forceinline__ void mma8(float* c, const uint32_t* a, const uint32_t* b) {
    asm volatile(
        "mma.sync.aligned.m16n8k8.row.col.f32.tf32.tf32.f32 "
        "{%0,%1,%2,%3}, {%4,%5,%6,%7}, {%8,%9}, {%0,%1,%2,%3};\n"
        : "+f"(c[0]), "+f"(c[1]), "+f"(c[2]), "+f"(c[3])
        : "r"(a[0]), "r"(a[1]), "r"(a[2]), "r"(a[3]),
          "r"(b[0]), "r"(b[1]));
}
__device__ __forceinline__ float silu_f(float x) { return x / (1.0f + __expf(-x)); }
__device__ __forceinline__ uint32_t smem_u32(const void* p) {
    return (uint32_t)__cvta_generic_to_shared(p);
}
__device__ __forceinline__ void cp16(uint32_t dst, const void* src) {
    asm volatile("cp.async.cg.shared.global [%0], [%1], 16;" :: "r"(dst), "l"(src));
}
__device__ __forceinline__ void cp16_pred(uint32_t dst, const void* src, int valid) {
    int sz = valid ? 16 : 0;   // sz=0 zero-fills the 16B destination
    asm volatile("cp.async.cg.shared.global [%0], [%1], 16, %2;"
                 :: "r"(dst), "l"(src), "r"(sz));
}
#define CP_COMMIT() asm volatile("cp.async.commit_group;" ::: "memory")
#define CP_WAIT1()  asm volatile("cp.async.wait_group 1;"  ::: "memory")

// ---------------- launch 1: fused prep (zero out + round x + init perm) ----------------
__global__ void prep_kernel(const float4* __restrict__ x, float4* __restrict__ out) {
    int i = blockIdx.x * blockDim.x + threadIdx.x;
    if (i < N_TOKENS * D_MODEL / 4) {
        out[i] = make_float4(0.f, 0.f, 0.f, 0.f);
        float4 v = x[i];
        uint4 u;
        u.x = f2tf(v.x); u.y = f2tf(v.y); u.z = f2tf(v.z); u.w = f2tf(v.w);
        *(uint4*)&g_Xr[(size_t)i * 4] = u;
    }
    if (i < MAX_SLOTS) g_perm[i] = -1;
}

// ---------------- launch 2: count + scan (single block) ----------------
__global__ void scan_count_kernel(const int* __restrict__ eidx) {
    __shared__ int hist[8][N_EXPERTS];
    const int tid = threadIdx.x;
    const int wid = tid >> 5;
    if (tid < 128) ((int*)hist)[tid] = 0;
    __syncthreads();
    const int4* e4 = (const int4*)eidx;
    for (int i = tid; i < A_TOTAL / 4; i += 256) {
        int4 e = e4[i];
        atomicAdd(&hist[wid][e.x], 1);
        atomicAdd(&hist[wid][e.y], 1);
        atomicAdd(&hist[wid][e.z], 1);
        atomicAdd(&hist[wid][e.w], 1);
    }
    __syncthreads();
    if (tid == 0) {
        for (int i = 0; i < MAX_MTILES; i++) g_tile_expert[i] = -1;
        int acc = 0;
        for (int e = 0; e < N_EXPERTS; e++) {
            int cnt = 0;
            for (int w = 0; w < 8; w++) cnt += hist[w][e];
            g_offsets[e] = acc;
            int nt = (cnt + BM - 1) / BM;
            int t0 = acc / BM;
            for (int i = 0; i < nt; i++) g_tile_expert[t0 + i] = e;
            acc += nt * BM;
        }
    }
}

// ---------------- launch 3: scatter ----------------
__global__ void scatter_kernel(const int* __restrict__ eidx,
                               const float* __restrict__ ew) {
    int i = blockIdx.x * blockDim.x + threadIdx.x;
    if (i < A_TOTAL) {
        int e = eidx[i];
        int p = atomicAdd(&g_offsets[e], 1);
        g_perm[p] = i / TOP_K;
        g_wgt[p]  = ew[i];
    }
}

// ---------------- launch 4: GEMM1: H = silu(X@W1) * (X@W2) ----------------
// grid (D_FF/BN=22, 144), 256 thr. Warps 2(m) x 4(n); warp tile 64x32.
__global__ void __launch_bounds__(256)
gemm1_kernel(const float* __restrict__ w1,
             const float* __restrict__ w2) {
    const int mt = blockIdx.y;
    const int e  = g_tile_expert[mt];
    if (e < 0) return;
    const int nb   = blockIdx.x * BN;
    const int row0 = mt * BM;

    extern __shared__ float smem[];
    float* sA  = smem;                       // 2 * A_STAGE
    float* sB1 = sA  + 2 * A_STAGE;          // 2 * B_STAGE
    float* sB2 = sB1 + 2 * B_STAGE;

    const int tid  = threadIdx.x;
    const int lane = tid & 31;
    const int wid  = tid >> 5;
    const int wm   = wid >> 2;      // 0..1
    const int wn   = wid & 3;       // 0..3
    const int g    = lane >> 2;
    const int t    = lane & 3;

    // A loader: 4 tasks. q = tid + 256j -> m = q>>3 (0..127), kq = q&7
    const float* apg[4];
    int av[4];
    uint32_t dA[4];
#pragma unroll
    for (int j = 0; j < 4; j++) {
        const int q = tid + 256 * j;
        const int m = q >> 3, kq = q & 7;
        const int tok = g_perm[row0 + m];
        av[j]  = (tok >= 0);
        apg[j] = g_Xr + (size_t)(tok < 0 ? 0 : tok) * D_MODEL + kq * 4;
        dA[j]  = smem_u32(sA + m * A_STRIDE + kq * 4);
    }
    // B loader: 4 tasks per matrix. q = tid + 256j -> k = q>>5 (0..31), nq = q&31
    const float* b1g[4];
    const float* b2g[4];
    uint32_t dB1[4], dB2[4];
#pragma unroll
    for (int j = 0; j < 4; j++) {
        const int q = tid + 256 * j;
        const int k = q >> 5, nq = q & 31;
        b1g[j] = w1 + (size_t)e * D_MODEL * D_FF + (size_t)k * D_FF + nb + nq * 4;
        b2g[j] = w2 + (size_t)e * D_MODEL * D_FF + (size_t)k * D_FF + nb + nq * 4;
        dB1[j] = smem_u32(sB1 + k * B_STRIDE + nq * 4);
        dB2[j] = smem_u32(sB2 + k * B_STRIDE + nq * 4);
    }

    const int KT = D_MODEL / BK;   // 32

    auto issue = [&](int kt) {
        if (kt < KT) {
            const int s = kt & 1;
            const int kg = kt * BK;
#pragma unroll
            for (int j = 0; j < 4; j++)
                cp16_pred(dA[j] + s * A_STAGE * 4, apg[j] + kg, av[j]);
#pragma unroll
            for (int j = 0; j < 4; j++) {
                cp16(dB1[j] + s * B_STAGE * 4, b1g[j] + (size_t)kg * D_FF);
                cp16(dB2[j] + s * B_STAGE * 4, b2g[j] + (size_t)kg * D_FF);
            }
        }
        CP_COMMIT();
    };

    float accg[4][4][4] = {};
    float accv[4][4][4] = {};

    issue(0); issue(1);

    for (int kt = 0; kt < KT; kt++) {
        CP_WAIT1();
        __syncthreads();

        const int s = kt & 1;
        const float* As  = sA  + s * A_STAGE;
        const float* B1s = sB1 + s * B_STAGE;
        const float* B2s = sB2 + s * B_STAGE;

#pragma unroll
        for (int ks = 0; ks < 4; ks++) {
            const int kk = ks * 8;
            uint32_t a[4][4];
#pragma unroll
            for (int mi = 0; mi < 4; mi++) {
                const int mr = wm * 64 + mi * 16;
                a[mi][0] = __float_as_uint(As[(mr + g    ) * A_STRIDE + kk + t    ]);
                a[mi][1] = __float_as_uint(As[(mr + g + 8) * A_STRIDE + kk + t    ]);
                a[mi][2] = __float_as_uint(As[(mr + g    ) * A_STRIDE + kk + t + 4]);
                a[mi][3] = __float_as_uint(As[(mr + g + 8) * A_STRIDE + kk + t + 4]);
            }
#pragma unroll
            for (int ni = 0; ni < 4; ni++) {
                const int nc = wn * 32 + ni * 8 + g;
                uint32_t b1[2], b2[2];
                b1[0] = f2tf(B1s[(kk + t    ) * B_STRIDE + nc]);
                b1[1] = f2tf(B1s[(kk + t + 4) * B_STRIDE + nc]);
                b2[0] = f2tf(B2s[(kk + t    ) * B_STRIDE + nc]);
                b2[1] = f2tf(B2s[(kk + t + 4) * B_STRIDE + nc]);
#pragma unroll
                for (int mi = 0; mi < 4; mi++) {
                    mma8(accg[mi][ni], a[mi], b1);
                    mma8(accv[mi][ni], a[mi], b2);
                }
            }
        }
        __syncthreads();
        issue(kt + 2);
    }

    // epilogue: SwiGLU -> g_H (tf32-rounded so GEMM2 loads raw)
#pragma unroll
    for (int mi = 0; mi < 4; mi++) {
        const int r = wm * 64 + mi * 16 + g;
        const size_t h0 = (size_t)(row0 + r)     * D_FF;
        const size_t h8 = (size_t)(row0 + r + 8) * D_FF;
#pragma unroll
        for (int ni = 0; ni < 4; ni++) {
            const int c = nb + wn * 32 + ni * 8 + 2 * t;
            uint2 v0, v8;
            v0.x = f2tf(silu_f(accg[mi][ni][0]) * accv[mi][ni][0]);
            v0.y = f2tf(silu_f(accg[mi][ni][1]) * accv[mi][ni][1]);
            v8.x = f2tf(silu_f(accg[mi][ni][2]) * accv[mi][ni][2]);
            v8.y = f2tf(silu_f(accg[mi][ni][3]) * accv[mi][ni][3]);
            *(uint2*)&g_H[h0 + c] = v0;
            *(uint2*)&g_H[h8 + c] = v8;
        }
    }
}

// ---------------- launch 5: GEMM2: out += wgt * (H @ W3) ----------------
// grid (D_MODEL/BN=8, 144), 256 thr, 2 CTAs/SM.
__global__ void __launch_bounds__(256, 2)
gemm2_kernel(const float* __restrict__ w3, float* __restrict__ out) {
    const int mt = blockIdx.y;
    const int e  = g_tile_expert[mt];
    if (e < 0) return;
    const int nb   = blockIdx.x * BN;
    const int row0 = mt * BM;

    extern __shared__ float smem[];
    float* sA = smem;
    float* sB = sA + 2 * A_STAGE;

    const int tid  = threadIdx.x;
    const int lane = tid & 31;
    const int wid  = tid >> 5;
    const int wm   = wid >> 2;
    const int wn   = wid & 3;
    const int g    = lane >> 2;
    const int t    = lane & 3;

    const float* apg[4];
    uint32_t dA[4];
#pragma unroll
    for (int j = 0; j < 4; j++) {
        const int q = tid + 256 * j;
        const int m = q >> 3, kq = q & 7;
        apg[j] = g_H + (size_t)(row0 + m) * D_FF + kq * 4;   // pad rows are zero
        dA[j]  = smem_u32(sA + m * A_STRIDE + kq * 4);
    }
    const float* bg[4];
    uint32_t dB[4];
#pragma unroll
    for (int j = 0; j < 4; j++) {
        const int q = tid + 256 * j;
        const int k = q >> 5, nq = q & 31;
        bg[j] = w3 + (size_t)e * D_FF * D_MODEL + (size_t)k * D_MODEL + nb + nq * 4;
        dB[j] = smem_u32(sB + k * B_STRIDE + nq * 4);
    }

    const int KT = D_FF / BK;   // 88

    auto issue = [&](int kt) {
        if (kt < KT) {
            const int s = kt & 1;
            const int kg = kt * BK;
#pragma unroll
            for (int j = 0; j < 4; j++)
                cp16(dA[j] + s * A_STAGE * 4, apg[j] + kg);
#pragma unroll
            for (int j = 0; j < 4; j++)
                cp16(dB[j] + s * B_STAGE * 4, bg[j] + (size_t)kg * D_MODEL);
        }
        CP_COMMIT();
    };

    float acc[4][4][4] = {};

    issue(0); issue(1);

    for (int kt = 0; kt < KT; kt++) {
        CP_WAIT1();
        __syncthreads();

        const int s = kt & 1;
        const float* As = sA + s * A_STAGE;
        const float* Bs = sB + s * B_STAGE;

#pragma unroll
        for (int ks = 0; ks < 4; ks++) {
            const int kk = ks * 8;
            uint32_t a[4][4];
#pragma unroll
            for (int mi = 0; mi < 4; mi++) {
                const int mr = wm * 64 + mi * 16;
                a[mi][0] = __float_as_uint(As[(mr + g    ) * A_STRIDE + kk + t    ]);
                a[mi][1] = __float_as_uint(As[(mr + g + 8) * A_STRIDE + kk + t    ]);
                a[mi][2] = __float_as_uint(As[(mr + g    ) * A_STRIDE + kk + t + 4]);
                a[mi][3] = __float_as_uint(As[(mr + g + 8) * A_STRIDE + kk + t + 4]);
            }
#pragma unroll
            for (int ni = 0; ni < 4; ni++) {
                const int nc = wn * 32 + ni * 8 + g;
                uint32_t b[2];
                b[0] = f2tf(Bs[(kk + t    ) * B_STRIDE + nc]);
                b[1] = f2tf(Bs[(kk + t + 4) * B_STRIDE + nc]);
#pragma unroll
                for (int mi = 0; mi < 4; mi++)
                    mma8(acc[mi][ni], a[mi], b);
            }
        }
        __syncthreads();
        issue(kt + 2);
    }

    // epilogue: weighted scatter-add (2 commutative adds per token -> deterministic)
#pragma unroll
    for (int mi = 0; mi < 4; mi++) {
        const int r  = wm * 64 + mi * 16 + g;
        const int s0 = row0 + r;
        const int s8 = s0 + 8;
        const int tk0 = g_perm[s0];
        const int tk8 = g_perm[s8];
        const float wt0 = (tk0 >= 0) ? g_wgt[s0] : 0.f;
        const float wt8 = (tk8 >= 0) ? g_wgt[s8] : 0.f;
#pragma unroll
        for (int ni = 0; ni < 4; ni++) {
            const int c = nb + wn * 32 + ni * 8 + 2 * t;
            if (tk0 >= 0) {
                atomicAdd(&out[(size_t)tk0 * D_MODEL + c    ], acc[mi][ni][0] * wt0);
                atomicAdd(&out[(size_t)tk0 * D_MODEL + c + 1], acc[mi][ni][1] * wt0);
            }
            if (tk8 >= 0) {
                atomicAdd(&out[(size_t)tk8 * D_MODEL + c    ], acc[mi][ni][2] * wt8);
                atomicAdd(&out[(size_t)tk8 * D_MODEL + c + 1], acc[mi][ni][3] * wt8);
            }
        }
    }
}

// ---------------- launch ----------------
extern "C" void kernel_launch(void* const* d_in, const int* in_sizes, int n_in,
                              void* d_out, int out_size) {
    const float* x    = (const float*)d_in[0];
    const int*   eidx = (const int*)  d_in[1];
    const float* ew   = (const float*)d_in[2];
    const float* w1   = (const float*)d_in[3];
    const float* w2   = (const float*)d_in[4];
    const float* w3   = (const float*)d_in[5];
    float* out = (float*)d_out;

    const int smem1 = 2 * (A_STAGE + 2 * B_STAGE) * 4;   // 106496 B
    const int smem2 = 2 * (A_STAGE + B_STAGE) * 4;       //  71680 B
    static int attr_done = 0;
    if (!attr_done) {
        cudaFuncSetAttribute(gemm1_kernel, cudaFuncAttributeMaxDynamicSharedMemorySize, smem1);
        cudaFuncSetAttribute(gemm2_kernel, cudaFuncAttributeMaxDynamicSharedMemorySize, smem2);
        attr_done = 1;
    }

    prep_kernel<<<(N_TOKENS * D_MODEL / 4 + 255) / 256, 256>>>((const float4*)x, (float4*)out);
    scan_count_kernel<<<1, 256>>>(eidx);
    scatter_kernel<<<(A_TOTAL + 255) / 256, 256>>>(eidx, ew);

    gemm1_kernel<<<dim3(D_FF / BN, MAX_MTILES), 256, smem1>>>(w1, w2);
    gemm2_kernel<<<dim3(D_MODEL / BN, MAX_MTILES), 256, smem2>>>(w3, out);
}

// round 9
// speedup vs baseline: 1.1706x; 1.0022x over previous
#include <cuda_runtime.h>
#include <cstdint>

#define N_EXPERTS 16
#define D_MODEL   1024
#define D_FF      2816
#define N_TOKENS  8192
#define TOP_K     2
#define A_TOTAL   (N_TOKENS * TOP_K)

#define BM 128
#define BK 32
#define BN 128

#define A_STRIDE 36      // [m][k] row stride: bank (4g+t)%32 distinct -> conflict-free frags
#define B_STRIDE 136     // [k][n] row stride: bank (8t+g)%32 distinct -> conflict-free frags
#define A_STAGE (BM * A_STRIDE)   // 4608 floats
#define B_STAGE (BK * B_STRIDE)   // 4352 floats

#define MAX_SLOTS  (A_TOTAL + N_EXPERTS * BM)  // 18432
#define MAX_MTILES (MAX_SLOTS / BM)            // 144

// ---------------- scratch ----------------
__device__ int   g_perm[MAX_SLOTS];
__device__ float g_wgt[MAX_SLOTS];
__device__ int   g_offsets[N_EXPERTS];
__device__ int   g_tile_expert[MAX_MTILES];
__device__ float g_Xr[(size_t)N_TOKENS * D_MODEL];   // tf32-pre-rounded x
__device__ float g_H[(size_t)MAX_SLOTS * D_FF];      // SwiGLU activations (tf32-rounded)

// ---------------- helpers ----------------
__device__ __forceinline__ uint32_t f2tf(float f) {
    uint32_t r;
    asm("cvt.rna.tf32.f32 %0, %1;" : "=r"(r) : "f"(f));
    return r;
}
// NOTE: not volatile — register-only outputs; lets ptxas interleave LDS with MMA streams
__device__ __forceinline__ void mma8(float* c, const uint32_t* a, const uint32_t* b) {
    asm("mma.sync.aligned.m16n8k8.row.col.f32.tf32.tf32.f32 "
        "{%0,%1,%2,%3}, {%4,%5,%6,%7}, {%8,%9}, {%0,%1,%2,%3};\n"
        : "+f"(c[0]), "+f"(c[1]), "+f"(c[2]), "+f"(c[3])
        : "r"(a[0]), "r"(a[1]), "r"(a[2]), "r"(a[3]),
          "r"(b[0]), "r"(b[1]));
}
__device__ __forceinline__ float silu_f(float x) { return x / (1.0f + __expf(-x)); }
__device__ __forceinline__ uint32_t smem_u32(const void* p) {
    return (uint32_t)__cvta_generic_to_shared(p);
}
__device__ __forceinline__ void cp16(uint32_t dst, const void* src) {
    asm volatile("cp.async.cg.shared.global [%0], [%1], 16;" :: "r"(dst), "l"(src));
}
__device__ __forceinline__ void cp16_pred(uint32_t dst, const void* src, int valid) {
    int sz = valid ? 16 : 0;   // sz=0 zero-fills the 16B destination
    asm volatile("cp.async.cg.shared.global [%0], [%1], 16, %2;"
                 :: "r"(dst), "l"(src), "r"(sz));
}
#define CP_COMMIT() asm volatile("cp.async.commit_group;" ::: "memory")
#define CP_WAIT1()  asm volatile("cp.async.wait_group 1;"  ::: "memory")

// ---------------- launch 1: fused prep (zero out + round x + init perm) ----------------
__global__ void prep_kernel(const float4* __restrict__ x, float4* __restrict__ out) {
    int i = blockIdx.x * blockDim.x + threadIdx.x;
    if (i < N_TOKENS * D_MODEL / 4) {
        out[i] = make_float4(0.f, 0.f, 0.f, 0.f);
        float4 v = x[i];
        uint4 u;
        u.x = f2tf(v.x); u.y = f2tf(v.y); u.z = f2tf(v.z); u.w = f2tf(v.w);
        *(uint4*)&g_Xr[(size_t)i * 4] = u;
    }
    if (i < MAX_SLOTS) g_perm[i] = -1;
}

// ---------------- launch 2: count + scan (single block) ----------------
__global__ void scan_count_kernel(const int* __restrict__ eidx) {
    __shared__ int hist[8][N_EXPERTS];
    const int tid = threadIdx.x;
    const int wid = tid >> 5;
    if (tid < 128) ((int*)hist)[tid] = 0;
    __syncthreads();
    const int4* e4 = (const int4*)eidx;
    for (int i = tid; i < A_TOTAL / 4; i += 256) {
        int4 e = e4[i];
        atomicAdd(&hist[wid][e.x], 1);
        atomicAdd(&hist[wid][e.y], 1);
        atomicAdd(&hist[wid][e.z], 1);
        atomicAdd(&hist[wid][e.w], 1);
    }
    __syncthreads();
    if (tid == 0) {
        for (int i = 0; i < MAX_MTILES; i++) g_tile_expert[i] = -1;
        int acc = 0;
        for (int e = 0; e < N_EXPERTS; e++) {
            int cnt = 0;
            for (int w = 0; w < 8; w++) cnt += hist[w][e];
            g_offsets[e] = acc;
            int nt = (cnt + BM - 1) / BM;
            int t0 = acc / BM;
            for (int i = 0; i < nt; i++) g_tile_expert[t0 + i] = e;
            acc += nt * BM;
        }
    }
}

// ---------------- launch 3: scatter ----------------
__global__ void scatter_kernel(const int* __restrict__ eidx,
                               const float* __restrict__ ew) {
    int i = blockIdx.x * blockDim.x + threadIdx.x;
    if (i < A_TOTAL) {
        int e = eidx[i];
        int p = atomicAdd(&g_offsets[e], 1);
        g_perm[p] = i / TOP_K;
        g_wgt[p]  = ew[i];
    }
}

// ---------------- launch 4: GEMM1: H = silu(X@W1) * (X@W2) ----------------
// grid (D_FF/BN=22, 144), 512 thr (16 warps). Warps 4(m) x 4(n); warp tile 32x32.
__global__ void __launch_bounds__(512)
gemm1_kernel(const float* __restrict__ w1,
             const float* __restrict__ w2) {
    const int mt = blockIdx.y;
    const int e  = g_tile_expert[mt];
    if (e < 0) return;
    const int nb   = blockIdx.x * BN;
    const int row0 = mt * BM;

    extern __shared__ float smem[];
    float* sA  = smem;                       // 2 * A_STAGE
    float* sB1 = sA  + 2 * A_STAGE;          // 2 * B_STAGE
    float* sB2 = sB1 + 2 * B_STAGE;

    const int tid  = threadIdx.x;
    const int lane = tid & 31;
    const int wid  = tid >> 5;
    const int wm   = wid >> 2;      // 0..3
    const int wn   = wid & 3;       // 0..3
    const int g    = lane >> 2;
    const int t    = lane & 3;

    // A loader: 2 tasks. q = tid + 512j -> m = q>>3 (0..127), kq = q&7
    const float* apg[2];
    int av[2];
    uint32_t dA[2];
#pragma unroll
    for (int j = 0; j < 2; j++) {
        const int q = tid + 512 * j;
        const int m = q >> 3, kq = q & 7;
        const int tok = g_perm[row0 + m];
        av[j]  = (tok >= 0);
        apg[j] = g_Xr + (size_t)(tok < 0 ? 0 : tok) * D_MODEL + kq * 4;
        dA[j]  = smem_u32(sA + m * A_STRIDE + kq * 4);
    }
    // B loader: 2 tasks per matrix. q = tid + 512j -> k = q>>5 (0..31), nq = q&31
    const float* b1g[2];
    const float* b2g[2];
    uint32_t dB1[2], dB2[2];
#pragma unroll
    for (int j = 0; j < 2; j++) {
        const int q = tid + 512 * j;
        const int k = q >> 5, nq = q & 31;
        b1g[j] = w1 + (size_t)e * D_MODEL * D_FF + (size_t)k * D_FF + nb + nq * 4;
        b2g[j] = w2 + (size_t)e * D_MODEL * D_FF + (size_t)k * D_FF + nb + nq * 4;
        dB1[j] = smem_u32(sB1 + k * B_STRIDE + nq * 4);
        dB2[j] = smem_u32(sB2 + k * B_STRIDE + nq * 4);
    }

    const int KT = D_MODEL / BK;   // 32

    auto issue = [&](int kt) {
        if (kt < KT) {
            const int s = kt & 1;
            const int kg = kt * BK;
#pragma unroll
            for (int j = 0; j < 2; j++)
                cp16_pred(dA[j] + s * A_STAGE * 4, apg[j] + kg, av[j]);
#pragma unroll
            for (int j = 0; j < 2; j++) {
                cp16(dB1[j] + s * B_STAGE * 4, b1g[j] + (size_t)kg * D_FF);
                cp16(dB2[j] + s * B_STAGE * 4, b2g[j] + (size_t)kg * D_FF);
            }
        }
        CP_COMMIT();
    };

    float accg[2][4][4] = {};
    float accv[2][4][4] = {};

    issue(0); issue(1);

    for (int kt = 0; kt < KT; kt++) {
        CP_WAIT1();
        __syncthreads();

        const int s = kt & 1;
        const float* As  = sA  + s * A_STAGE;
        const float* B1s = sB1 + s * B_STAGE;
        const float* B2s = sB2 + s * B_STAGE;

#pragma unroll
        for (int ks = 0; ks < 4; ks++) {
            const int kk = ks * 8;
            uint32_t a[2][4];
#pragma unroll
            for (int mi = 0; mi < 2; mi++) {
                const int mr = wm * 32 + mi * 16;
                a[mi][0] = __float_as_uint(As[(mr + g    ) * A_STRIDE + kk + t    ]);
                a[mi][1] = __float_as_uint(As[(mr + g + 8) * A_STRIDE + kk + t    ]);
                a[mi][2] = __float_as_uint(As[(mr + g    ) * A_STRIDE + kk + t + 4]);
                a[mi][3] = __float_as_uint(As[(mr + g + 8) * A_STRIDE + kk + t + 4]);
            }
#pragma unroll
            for (int ni = 0; ni < 4; ni++) {
                const int nc = wn * 32 + ni * 8 + g;
                uint32_t b1[2], b2[2];
                b1[0] = f2tf(B1s[(kk + t    ) * B_STRIDE + nc]);
                b1[1] = f2tf(B1s[(kk + t + 4) * B_STRIDE + nc]);
                b2[0] = f2tf(B2s[(kk + t    ) * B_STRIDE + nc]);
                b2[1] = f2tf(B2s[(kk + t + 4) * B_STRIDE + nc]);
#pragma unroll
                for (int mi = 0; mi < 2; mi++) {
                    mma8(accg[mi][ni], a[mi], b1);
                    mma8(accv[mi][ni], a[mi], b2);
                }
            }
        }
        __syncthreads();
        issue(kt + 2);
    }

    // epilogue: SwiGLU -> g_H (tf32-rounded so GEMM2 loads raw)
#pragma unroll
    for (int mi = 0; mi < 2; mi++) {
        const int r = wm * 32 + mi * 16 + g;
        const size_t h0 = (size_t)(row0 + r)     * D_FF;
        const size_t h8 = (size_t)(row0 + r + 8) * D_FF;
#pragma unroll
        for (int ni = 0; ni < 4; ni++) {
            const int c = nb + wn * 32 + ni * 8 + 2 * t;
            uint2 v0, v8;
            v0.x = f2tf(silu_f(accg[mi][ni][0]) * accv[mi][ni][0]);
            v0.y = f2tf(silu_f(accg[mi][ni][1]) * accv[mi][ni][1]);
            v8.x = f2tf(silu_f(accg[mi][ni][2]) * accv[mi][ni][2]);
            v8.y = f2tf(silu_f(accg[mi][ni][3]) * accv[mi][ni][3]);
            *(uint2*)&g_H[h0 + c] = v0;
            *(uint2*)&g_H[h8 + c] = v8;
        }
    }
}

// ---------------- launch 5: GEMM2: out += wgt * (H @ W3) ----------------
// grid (D_MODEL/BN=8, 144), 256 thr, 2 CTAs/SM.
__global__ void __launch_bounds__(256, 2)
gemm2_kernel(const float* __restrict__ w3, float* __restrict__ out) {
    const int mt = blockIdx.y;
    const int e  = g_tile_expert[mt];
    if (e < 0) return;
    const int nb   = blockIdx.x * BN;
    const int row0 = mt * BM;

    extern __shared__ float smem[];
    float* sA = smem;
    float* sB = sA + 2 * A_STAGE;

    const int tid  = threadIdx.x;
    const int lane = tid & 31;
    const int wid  = tid >> 5;
    const int wm   = wid >> 2;
    const int wn   = wid & 3;
    const int g    = lane >> 2;
    const int t    = lane & 3;

    const float* apg[4];
    uint32_t dA[4];
#pragma unroll
    for (int j = 0; j < 4; j++) {
        const int q = tid + 256 * j;
        const int m = q >> 3, kq = q & 7;
        apg[j] = g_H + (size_t)(row0 + m) * D_FF + kq * 4;   // pad rows are zero
        dA[j]  = smem_u32(sA + m * A_STRIDE + kq * 4);
    }
    const float* bg[4];
    uint32_t dB[4];
#pragma unroll
    for (int j = 0; j < 4; j++) {
        const int q = tid + 256 * j;
        const int k = q >> 5, nq = q & 31;
        bg[j] = w3 + (size_t)e * D_FF * D_MODEL + (size_t)k * D_MODEL + nb + nq * 4;
        dB[j] = smem_u32(sB + k * B_STRIDE + nq * 4);
    }

    const int KT = D_FF / BK;   // 88

    auto issue = [&](int kt) {
        if (kt < KT) {
            const int s = kt & 1;
            const int kg = kt * BK;
#pragma unroll
            for (int j = 0; j < 4; j++)
                cp16(dA[j] + s * A_STAGE * 4, apg[j] + kg);
#pragma unroll
            for (int j = 0; j < 4; j++)
                cp16(dB[j] + s * B_STAGE * 4, bg[j] + (size_t)kg * D_MODEL);
        }
        CP_COMMIT();
    };

    float acc[4][4][4] = {};

    issue(0); issue(1);

    for (int kt = 0; kt < KT; kt++) {
        CP_WAIT1();
        __syncthreads();

        const int s = kt & 1;
        const float* As = sA + s * A_STAGE;
        const float* Bs = sB + s * B_STAGE;

#pragma unroll
        for (int ks = 0; ks < 4; ks++) {
            const int kk = ks * 8;
            uint32_t a[4][4];
#pragma unroll
            for (int mi = 0; mi < 4; mi++) {
                const int mr = wm * 64 + mi * 16;
                a[mi][0] = __float_as_uint(As[(mr + g    ) * A_STRIDE + kk + t    ]);
                a[mi][1] = __float_as_uint(As[(mr + g + 8) * A_STRIDE + kk + t    ]);
                a[mi][2] = __float_as_uint(As[(mr + g    ) * A_STRIDE + kk + t + 4]);
                a[mi][3] = __float_as_uint(As[(mr + g + 8) * A_STRIDE + kk + t + 4]);
            }
#pragma unroll
            for (int ni = 0; ni < 4; ni++) {
                const int nc = wn * 32 + ni * 8 + g;
                uint32_t b[2];
                b[0] = f2tf(Bs[(kk + t    ) * B_STRIDE + nc]);
                b[1] = f2tf(Bs[(kk + t + 4) * B_STRIDE + nc]);
#pragma unroll
                for (int mi = 0; mi < 4; mi++)
                    mma8(acc[mi][ni], a[mi], b);
            }
        }
        __syncthreads();
        issue(kt + 2);
    }

    // epilogue: weighted scatter-add (2 commutative adds per token -> deterministic)
#pragma unroll
    for (int mi = 0; mi < 4; mi++) {
        const int r  = wm * 64 + mi * 16 + g;
        const int s0 = row0 + r;
        const int s8 = s0 + 8;
        const int tk0 = g_perm[s0];
        const int tk8 = g_perm[s8];
        const float wt0 = (tk0 >= 0) ? g_wgt[s0] : 0.f;
        const float wt8 = (tk8 >= 0) ? g_wgt[s8] : 0.f;
#pragma unroll
        for (int ni = 0; ni < 4; ni++) {
            const int c = nb + wn * 32 + ni * 8 + 2 * t;
            if (tk0 >= 0) {
                atomicAdd(&out[(size_t)tk0 * D_MODEL + c    ], acc[mi][ni][0] * wt0);
                atomicAdd(&out[(size_t)tk0 * D_MODEL + c + 1], acc[mi][ni][1] * wt0);
            }
            if (tk8 >= 0) {
                atomicAdd(&out[(size_t)tk8 * D_MODEL + c    ], acc[mi][ni][2] * wt8);
                atomicAdd(&out[(size_t)tk8 * D_MODEL + c + 1], acc[mi][ni][3] * wt8);
            }
        }
    }
}

// ---------------- launch ----------------
extern "C" void kernel_launch(void* const* d_in, const int* in_sizes, int n_in,
                              void* d_out, int out_size) {
    const float* x    = (const float*)d_in[0];
    const int*   eidx = (const int*)  d_in[1];
    const float* ew   = (const float*)d_in[2];
    const float* w1   = (const float*)d_in[3];
    const float* w2   = (const float*)d_in[4];
    const float* w3   = (const float*)d_in[5];
    float* out = (float*)d_out;

    const int smem1 = 2 * (A_STAGE + 2 * B_STAGE) * 4;   // 106496 B
    const int smem2 = 2 * (A_STAGE + B_STAGE) * 4;       //  71680 B
    static int attr_done = 0;
    if (!attr_done) {
        cudaFuncSetAttribute(gemm1_kernel, cudaFuncAttributeMaxDynamicSharedMemorySize, smem1);
        cudaFuncSetAttribute(gemm2_kernel, cudaFuncAttributeMaxDynamicSharedMemorySize, smem2);
        attr_done = 1;
    }

    prep_kernel<<<(N_TOKENS * D_MODEL / 4 + 255) / 256, 256>>>((const float4*)x, (float4*)out);
    scan_count_kernel<<<1, 256>>>(eidx);
    scatter_kernel<<<(A_TOTAL + 255) / 256, 256>>>(eidx, ew);

    gemm1_kernel<<<dim3(D_FF / BN, MAX_MTILES), 512, smem1>>>(w1, w2);
    gemm2_kernel<<<dim3(D_MODEL / BN, MAX_MTILES), 256, smem2>>>(w3, out);
}

// round 10
// speedup vs baseline: 2.3072x; 1.9708x over previous
#include <cuda_runtime.h>
#include <cuda_fp16.h>
#include <cstdint>

#define N_EXPERTS 16
#define D_MODEL   1024
#define D_FF      2816
#define N_TOKENS  8192
#define TOP_K     2
#define A_TOTAL   (N_TOKENS * TOP_K)

#define BM 128
#define BK 32
#define BN 128

#define A_STH 40                   // A smem row stride (halves): ldmatrix conflict-free
#define B_STH 136                  // B smem row stride (halves): ldmatrix.trans conflict-free
#define A_STAGE_H (BM * A_STH)     // 5120 halves = 10240 B
#define B_STAGE_H (BK * B_STH)     // 4352 halves =  8704 B

#define MAX_SLOTS  (A_TOTAL + N_EXPERTS * BM)  // 18432
#define MAX_MTILES (MAX_SLOTS / BM)            // 144

// ---------------- scratch (device globals) ----------------
__device__ int    g_perm[MAX_SLOTS];
__device__ float  g_wgt[MAX_SLOTS];
__device__ int    g_offsets[N_EXPERTS];
__device__ int    g_tile_expert[MAX_MTILES];
__device__ __half g_Xh[(size_t)N_TOKENS * D_MODEL];            // fp16 x
__device__ __half g_Hh[(size_t)MAX_SLOTS * D_FF];              // fp16 SwiGLU activations
__device__ __half g_W1h[(size_t)N_EXPERTS * D_MODEL * D_FF];   // fp16 weights
__device__ __half g_W2h[(size_t)N_EXPERTS * D_MODEL * D_FF];
__device__ __half g_W3h[(size_t)N_EXPERTS * D_FF * D_MODEL];

// ---------------- helpers ----------------
__device__ __forceinline__ void mma16(float* c, const uint32_t* a, const uint32_t* b) {
    asm("mma.sync.aligned.m16n8k16.row.col.f32.f16.f16.f32 "
        "{%0,%1,%2,%3}, {%4,%5,%6,%7}, {%8,%9}, {%0,%1,%2,%3};\n"
        : "+f"(c[0]), "+f"(c[1]), "+f"(c[2]), "+f"(c[3])
        : "r"(a[0]), "r"(a[1]), "r"(a[2]), "r"(a[3]),
          "r"(b[0]), "r"(b[1]));
}
__device__ __forceinline__ void ldsm4(uint32_t* r, uint32_t addr) {
    asm volatile("ldmatrix.sync.aligned.m8n8.x4.shared.b16 {%0,%1,%2,%3}, [%4];"
                 : "=r"(r[0]), "=r"(r[1]), "=r"(r[2]), "=r"(r[3]) : "r"(addr));
}
__device__ __forceinline__ void ldsm4t(uint32_t* r, uint32_t addr) {
    asm volatile("ldmatrix.sync.aligned.m8n8.x4.trans.shared.b16 {%0,%1,%2,%3}, [%4];"
                 : "=r"(r[0]), "=r"(r[1]), "=r"(r[2]), "=r"(r[3]) : "r"(addr));
}
__device__ __forceinline__ float silu_f(float x) { return x / (1.0f + __expf(-x)); }
__device__ __forceinline__ uint32_t smem_u32(const void* p) {
    return (uint32_t)__cvta_generic_to_shared(p);
}
__device__ __forceinline__ void cp16(uint32_t dst, const void* src) {
    asm volatile("cp.async.cg.shared.global [%0], [%1], 16;" :: "r"(dst), "l"(src));
}
__device__ __forceinline__ void cp16_pred(uint32_t dst, const void* src, int valid) {
    int sz = valid ? 16 : 0;   // sz=0 zero-fills the 16B destination
    asm volatile("cp.async.cg.shared.global [%0], [%1], 16, %2;"
                 :: "r"(dst), "l"(src), "r"(sz));
}
#define CP_COMMIT() asm volatile("cp.async.commit_group;" ::: "memory")
#define CP_WAIT1()  asm volatile("cp.async.wait_group 1;"  ::: "memory")

// ---------------- launch 1: convert everything to fp16 + zero output ----------------
#define WU ((size_t)N_EXPERTS * D_MODEL * D_FF / 8)   // 5,767,168 units of 8 floats
#define XU ((size_t)N_TOKENS * D_MODEL / 8)           // 1,048,576
#define CVT_UNITS (3 * WU + 2 * XU)

__device__ __forceinline__ void cvt8(const float4* __restrict__ src, __half* __restrict__ dst, size_t u) {
    float4 a = src[2 * u], b = src[2 * u + 1];
    __half2 h[4];
    h[0] = __floats2half2_rn(a.x, a.y);
    h[1] = __floats2half2_rn(a.z, a.w);
    h[2] = __floats2half2_rn(b.x, b.y);
    h[3] = __floats2half2_rn(b.z, b.w);
    *(uint4*)(dst + 8 * u) = *(uint4*)h;
}

__global__ void cvt_all_kernel(const float4* __restrict__ w1, const float4* __restrict__ w2,
                               const float4* __restrict__ w3, const float4* __restrict__ x,
                               float4* __restrict__ out) {
    size_t i = (size_t)blockIdx.x * blockDim.x + threadIdx.x;
    if (i < WU)                cvt8(w1, g_W1h, i);
    else if (i < 2 * WU)       cvt8(w2, g_W2h, i - WU);
    else if (i < 3 * WU)       cvt8(w3, g_W3h, i - 2 * WU);
    else if (i < 3 * WU + XU)  cvt8(x,  g_Xh,  i - 3 * WU);
    else if (i < CVT_UNITS) {
        size_t u = i - 3 * WU - XU;
        out[2 * u]     = make_float4(0.f, 0.f, 0.f, 0.f);
        out[2 * u + 1] = make_float4(0.f, 0.f, 0.f, 0.f);
    }
}

// ---------------- launch 2: count + scan + perm init (single block) ----------------
__global__ void scan_count_kernel(const int* __restrict__ eidx) {
    __shared__ int hist[8][N_EXPERTS];
    const int tid = threadIdx.x;
    const int wid = tid >> 5;
    if (tid < 128) ((int*)hist)[tid] = 0;
    for (int i = tid; i < MAX_SLOTS; i += 256) g_perm[i] = -1;
    __syncthreads();
    const int4* e4 = (const int4*)eidx;
    for (int i = tid; i < A_TOTAL / 4; i += 256) {
        int4 e = e4[i];
        atomicAdd(&hist[wid][e.x], 1);
        atomicAdd(&hist[wid][e.y], 1);
        atomicAdd(&hist[wid][e.z], 1);
        atomicAdd(&hist[wid][e.w], 1);
    }
    __syncthreads();
    if (tid == 0) {
        for (int i = 0; i < MAX_MTILES; i++) g_tile_expert[i] = -1;
        int acc = 0;
        for (int e = 0; e < N_EXPERTS; e++) {
            int cnt = 0;
            for (int w = 0; w < 8; w++) cnt += hist[w][e];
            g_offsets[e] = acc;
            int nt = (cnt + BM - 1) / BM;
            int t0 = acc / BM;
            for (int i = 0; i < nt; i++) g_tile_expert[t0 + i] = e;
            acc += nt * BM;
        }
    }
}

// ---------------- launch 3: scatter ----------------
__global__ void scatter_kernel(const int* __restrict__ eidx,
                               const float* __restrict__ ew) {
    int i = blockIdx.x * blockDim.x + threadIdx.x;
    if (i < A_TOTAL) {
        int e = eidx[i];
        int p = atomicAdd(&g_offsets[e], 1);
        g_perm[p] = i / TOP_K;
        g_wgt[p]  = ew[i];
    }
}

// ---------------- launch 4: GEMM1: H = silu(X@W1) * (X@W2), fp16 MMA ----------------
// grid (D_FF/BN=22, 144), 512 thr (16 warps). Warps 4(m) x 4(n); warp tile 32x32.
__global__ void __launch_bounds__(512)
gemm1_kernel() {
    const int mt = blockIdx.y;
    const int e  = g_tile_expert[mt];
    if (e < 0) return;
    const int nb   = blockIdx.x * BN;
    const int row0 = mt * BM;

    extern __shared__ __half smem[];
    __half* sA  = smem;                       // 2 * A_STAGE_H
    __half* sB1 = sA  + 2 * A_STAGE_H;        // 2 * B_STAGE_H
    __half* sB2 = sB1 + 2 * B_STAGE_H;

    const int tid  = threadIdx.x;
    const int lane = tid & 31;
    const int wid  = tid >> 5;
    const int wm   = wid >> 2;      // 0..3
    const int wn   = wid & 3;       // 0..3
    const int m0   = wm * 32;
    const int nG   = wn * 32;
    const int g    = lane >> 2;
    const int t    = lane & 3;

    // A cp.async loader: 1 task/thread: m = tid>>2 (0..127), 16B quad kq = tid&3
    const int mA = tid >> 2, kqA = tid & 3;
    const int tok = g_perm[row0 + mA];
    const int av  = (tok >= 0);
    const __half* apg = g_Xh + (size_t)(tok < 0 ? 0 : tok) * D_MODEL + kqA * 8;
    const uint32_t dA = smem_u32(sA + mA * A_STH + kqA * 8);
    // B loaders: 1 task/thread each: k = tid>>4 (0..31), 16B quad nq = tid&15
    const int kB = tid >> 4, nqB = tid & 15;
    const __half* b1g = g_W1h + (size_t)e * D_MODEL * D_FF + (size_t)kB * D_FF + nb + nqB * 8;
    const __half* b2g = g_W2h + (size_t)e * D_MODEL * D_FF + (size_t)kB * D_FF + nb + nqB * 8;
    const uint32_t dB1 = smem_u32(sB1 + kB * B_STH + nqB * 8);
    const uint32_t dB2 = smem_u32(sB2 + kB * B_STH + nqB * 8);

    // ldmatrix lane offsets
    const int laR = (lane & 7) + 8 * ((lane >> 3) & 1);   // row within 16
    const int laK = 8 * (lane >> 4);                      // k-half select
    const uint32_t aoff  = smem_u32(sA)  + ((m0 + laR) * A_STH + laK) * 2;
    const uint32_t b1off = smem_u32(sB1) + (laR * B_STH + nG + laK) * 2;  // laR->k row, laK->n+8 sel
    const uint32_t b2off = smem_u32(sB2) + (laR * B_STH + nG + laK) * 2;

    const int KT = D_MODEL / BK;   // 32

    auto issue = [&](int kt) {
        if (kt < KT) {
            const int s = kt & 1;
            const int kg = kt * BK;
            cp16_pred(dA + s * A_STAGE_H * 2, apg + kg, av);
            cp16(dB1 + s * B_STAGE_H * 2, b1g + (size_t)kg * D_FF);
            cp16(dB2 + s * B_STAGE_H * 2, b2g + (size_t)kg * D_FF);
        }
        CP_COMMIT();
    };

    float accg[2][4][4] = {};
    float accv[2][4][4] = {};

    issue(0); issue(1);

    for (int kt = 0; kt < KT; kt++) {
        CP_WAIT1();
        __syncthreads();

        const int s = kt & 1;
        const uint32_t aS  = aoff  + s * A_STAGE_H * 2;
        const uint32_t b1S = b1off + s * B_STAGE_H * 2;
        const uint32_t b2S = b2off + s * B_STAGE_H * 2;

#pragma unroll
        for (int kf = 0; kf < 2; kf++) {
            uint32_t af[2][4];
            ldsm4(af[0], aS + kf * 32);            // mi=0: +16 halves
            ldsm4(af[1], aS + kf * 32 + 16 * A_STH * 2);
#pragma unroll
            for (int nj = 0; nj < 2; nj++) {
                uint32_t bb1[4], bb2[4];
                ldsm4t(bb1, b1S + kf * 16 * B_STH * 2 + nj * 32);
                ldsm4t(bb2, b2S + kf * 16 * B_STH * 2 + nj * 32);
#pragma unroll
                for (int mi = 0; mi < 2; mi++) {
                    mma16(accg[mi][2 * nj],     af[mi], bb1);
                    mma16(accg[mi][2 * nj + 1], af[mi], bb1 + 2);
                    mma16(accv[mi][2 * nj],     af[mi], bb2);
                    mma16(accv[mi][2 * nj + 1], af[mi], bb2 + 2);
                }
            }
        }
        __syncthreads();
        issue(kt + 2);
    }

    // epilogue: SwiGLU -> g_Hh (fp16)
#pragma unroll
    for (int mi = 0; mi < 2; mi++) {
        const int r = m0 + mi * 16 + g;
        const size_t h0 = (size_t)(row0 + r)     * D_FF;
        const size_t h8 = (size_t)(row0 + r + 8) * D_FF;
#pragma unroll
        for (int ni = 0; ni < 4; ni++) {
            const int c = nb + nG + ni * 8 + 2 * t;
            *(__half2*)&g_Hh[h0 + c] = __floats2half2_rn(
                silu_f(accg[mi][ni][0]) * accv[mi][ni][0],
                silu_f(accg[mi][ni][1]) * accv[mi][ni][1]);
            *(__half2*)&g_Hh[h8 + c] = __floats2half2_rn(
                silu_f(accg[mi][ni][2]) * accv[mi][ni][2],
                silu_f(accg[mi][ni][3]) * accv[mi][ni][3]);
        }
    }
}

// ---------------- launch 5: GEMM2: out += wgt * (H @ W3), fp16 MMA ----------------
// grid (D_MODEL/BN=8, 144), 256 thr, 2 CTAs/SM. Warps 2(m) x 4(n); warp tile 64x32.
__global__ void __launch_bounds__(256, 2)
gemm2_kernel(float* __restrict__ out) {
    const int mt = blockIdx.y;
    const int e  = g_tile_expert[mt];
    if (e < 0) return;
    const int nb   = blockIdx.x * BN;
    const int row0 = mt * BM;

    extern __shared__ __half smem[];
    __half* sA = smem;                     // 2 * A_STAGE_H
    __half* sB = sA + 2 * A_STAGE_H;       // 2 * B_STAGE_H

    const int tid  = threadIdx.x;
    const int lane = tid & 31;
    const int wid  = tid >> 5;
    const int wm   = wid >> 2;      // 0..1
    const int wn   = wid & 3;       // 0..3
    const int m0   = wm * 64;
    const int nG   = wn * 32;
    const int g    = lane >> 2;
    const int t    = lane & 3;

    // A loader: 2 tasks: q = tid + 256j: m = q>>2, kq = q&3
    const __half* apg[2];
    uint32_t dA[2];
#pragma unroll
    for (int j = 0; j < 2; j++) {
        const int q = tid + 256 * j;
        const int m = q >> 2, kq = q & 3;
        apg[j] = g_Hh + (size_t)(row0 + m) * D_FF + kq * 8;
        dA[j]  = smem_u32(sA + m * A_STH + kq * 8);
    }
    // B loader: 2 tasks: q: k = q>>4, nq = q&15
    const __half* bg[2];
    uint32_t dB[2];
#pragma unroll
    for (int j = 0; j < 2; j++) {
        const int q = tid + 256 * j;
        const int k = q >> 4, nq = q & 15;
        bg[j] = g_W3h + (size_t)e * D_FF * D_MODEL + (size_t)k * D_MODEL + nb + nq * 8;
        dB[j] = smem_u32(sB + k * B_STH + nq * 8);
    }

    const int laR = (lane & 7) + 8 * ((lane >> 3) & 1);
    const int laK = 8 * (lane >> 4);
    const uint32_t aoff = smem_u32(sA) + ((m0 + laR) * A_STH + laK) * 2;
    const uint32_t boff = smem_u32(sB) + (laR * B_STH + nG + laK) * 2;

    const int KT = D_FF / BK;   // 88

    auto issue = [&](int kt) {
        if (kt < KT) {
            const int s = kt & 1;
            const int kg = kt * BK;
#pragma unroll
            for (int j = 0; j < 2; j++) cp16(dA[j] + s * A_STAGE_H * 2, apg[j] + kg);
#pragma unroll
            for (int j = 0; j < 2; j++) cp16(dB[j] + s * B_STAGE_H * 2, bg[j] + (size_t)kg * D_MODEL);
        }
        CP_COMMIT();
    };

    float acc[4][4][4] = {};

    issue(0); issue(1);

    for (int kt = 0; kt < KT; kt++) {
        CP_WAIT1();
        __syncthreads();

        const int s = kt & 1;
        const uint32_t aS = aoff + s * A_STAGE_H * 2;
        const uint32_t bS = boff + s * B_STAGE_H * 2;

#pragma unroll
        for (int kf = 0; kf < 2; kf++) {
            uint32_t af[4][4];
#pragma unroll
            for (int mi = 0; mi < 4; mi++)
                ldsm4(af[mi], aS + kf * 32 + mi * 16 * A_STH * 2);
#pragma unroll
            for (int nj = 0; nj < 2; nj++) {
                uint32_t bb[4];
                ldsm4t(bb, bS + kf * 16 * B_STH * 2 + nj * 32);
#pragma unroll
                for (int mi = 0; mi < 4; mi++) {
                    mma16(acc[mi][2 * nj],     af[mi], bb);
                    mma16(acc[mi][2 * nj + 1], af[mi], bb + 2);
                }
            }
        }
        __syncthreads();
        issue(kt + 2);
    }

    // epilogue: weighted scatter-add (exactly 2 commutative adds per token)
#pragma unroll
    for (int mi = 0; mi < 4; mi++) {
        const int r  = m0 + mi * 16 + g;
        const int s0 = row0 + r;
        const int s8 = s0 + 8;
        const int tk0 = g_perm[s0];
        const int tk8 = g_perm[s8];
        const float wt0 = (tk0 >= 0) ? g_wgt[s0] : 0.f;
        const float wt8 = (tk8 >= 0) ? g_wgt[s8] : 0.f;
#pragma unroll
        for (int ni = 0; ni < 4; ni++) {
            const int c = nb + nG + ni * 8 + 2 * t;
            if (tk0 >= 0) {
                atomicAdd(&out[(size_t)tk0 * D_MODEL + c    ], acc[mi][ni][0] * wt0);
                atomicAdd(&out[(size_t)tk0 * D_MODEL + c + 1], acc[mi][ni][1] * wt0);
            }
            if (tk8 >= 0) {
                atomicAdd(&out[(size_t)tk8 * D_MODEL + c    ], acc[mi][ni][2] * wt8);
                atomicAdd(&out[(size_t)tk8 * D_MODEL + c + 1], acc[mi][ni][3] * wt8);
            }
        }
    }
}

// ---------------- launch ----------------
extern "C" void kernel_launch(void* const* d_in, const int* in_sizes, int n_in,
                              void* d_out, int out_size) {
    const float* x    = (const float*)d_in[0];
    const int*   eidx = (const int*)  d_in[1];
    const float* ew   = (const float*)d_in[2];
    const float* w1   = (const float*)d_in[3];
    const float* w2   = (const float*)d_in[4];
    const float* w3   = (const float*)d_in[5];
    float* out = (float*)d_out;

    const int smem1 = (2 * A_STAGE_H + 4 * B_STAGE_H) * 2;   // 55296 B
    const int smem2 = (2 * A_STAGE_H + 2 * B_STAGE_H) * 2;   // 37888 B
    static int attr_done = 0;
    if (!attr_done) {
        cudaFuncSetAttribute(gemm1_kernel, cudaFuncAttributeMaxDynamicSharedMemorySize, smem1);
        cudaFuncSetAttribute(gemm2_kernel, cudaFuncAttributeMaxDynamicSharedMemorySize, smem2);
        attr_done = 1;
    }

    cvt_all_kernel<<<(unsigned)((CVT_UNITS + 255) / 256), 256>>>(
        (const float4*)w1, (const float4*)w2, (const float4*)w3, (const float4*)x, (float4*)out);
    scan_count_kernel<<<1, 256>>>(eidx);
    scatter_kernel<<<(A_TOTAL + 255) / 256, 256>>>(eidx, ew);

    gemm1_kernel<<<dim3(D_FF / BN, MAX_MTILES), 512, smem1>>>();
    gemm2_kernel<<<dim3(D_MODEL / BN, MAX_MTILES), 256, smem2>>>(out);
}